// round 5
// baseline (speedup 1.0000x reference)
#include <cuda_runtime.h>
#include <cuda_bf16.h>
#include <math.h>

// Problem constants (shapes are fixed by the dataset).
#define NN   25000      // nodes
#define EE   400000     // edges
#define ET   (EE + NN)  // edges + self loops
#define FIN  256        // input features
#define CC   32         // hidden per head
#define HH   12         // heads
#define HC   384        // HH*CC
#define NEG_SLOPE 0.2f
#define CHUNK 64        // edges per aggregation chunk

// ---------------- scratch (static device globals; allocation-free) ----------
__device__ float d_hx1[(size_t)NN * HC];   // x @ W1
__device__ float d_h1 [(size_t)NN * HC];   // elu(layer1 out)
__device__ float d_hx2[(size_t)NN * HC];   // h1 @ W2
__device__ float d_as1[NN * HH], d_ad1[NN * HH];
__device__ float d_as2[NN * HH], d_ad2[NN * HH];
__device__ float d_cnt[NN];
__device__ float d_loop_attr[(size_t)NN * CC];
__device__ float d_Ve[CC * HH];
__device__ float d_ae[(size_t)ET * HH];
__device__ int   d_deg[NN];
__device__ int   d_rowptr[NN + 1];
__device__ int   d_cursor[NN];
__device__ int   d_csr_src[ET];
__device__ int   d_csr_eid[ET];
__device__ int   d_esrc[EE];
__device__ int   d_edst[EE];
__device__ int   d_is64;

// ---------------- helpers ----------------------------------------------------
__device__ __forceinline__ unsigned enc_f(float f) {
    unsigned u = __float_as_uint(f);
    return (u & 0x80000000u) ? ~u : (u | 0x80000000u);
}
__device__ __forceinline__ float dec_f(unsigned k) {
    return (k & 0x80000000u) ? __uint_as_float(k & 0x7FFFFFFFu)
                             : __uint_as_float(~k);
}

// ---------------- edge-index dtype probe + conversion -------------------------
// JAX with x64 disabled silently downgrades int64 -> int32; detect which one
// we actually got. For int64 (values < 2^31) every odd int32 slot is the zero
// high word; for int32 those slots are random node indices.
__global__ void detect_kernel(const int* __restrict__ ei32) {
    if (threadIdx.x == 0) {
        int z = 1;
        #pragma unroll
        for (int i = 1; i < 64; i += 2) z &= (ei32[i] == 0);
        d_is64 = z;
    }
}

__global__ void convert_kernel(const int* __restrict__ ei32) {
    int e = blockIdx.x * blockDim.x + threadIdx.x;
    if (e >= EE) return;
    if (d_is64) {
        d_esrc[e] = ei32[2 * (size_t)e];
        d_edst[e] = ei32[2 * ((size_t)EE + e)];
    } else {
        d_esrc[e] = ei32[e];
        d_edst[e] = ei32[EE + e];
    }
}

// ---------------- preprocessing ----------------------------------------------
__global__ void init_kernel() {
    int i = blockIdx.x * blockDim.x + threadIdx.x;
    int stride = gridDim.x * blockDim.x;
    for (int j = i; j < NN; j += stride) { d_cnt[j] = 0.f; d_deg[j] = 0; }
    for (int j = i; j < NN * CC; j += stride) d_loop_attr[j] = 0.f;
}

// per-dst sum of edge_attr + incoming-edge count (for PyG fill_value='mean')
__global__ void edge_sums_kernel(const float* __restrict__ ea) {
    int idx = blockIdx.x * blockDim.x + threadIdx.x;
    if (idx >= EE * CC) return;
    int e = idx >> 5, c = idx & 31;
    int dst = d_edst[e];
    atomicAdd(&d_loop_attr[(size_t)dst * CC + c], ea[idx]);
    if (c == 0) atomicAdd(&d_cnt[dst], 1.f);
}

__global__ void loop_div_kernel() {
    int idx = blockIdx.x * blockDim.x + threadIdx.x;
    if (idx >= NN * CC) return;
    d_loop_attr[idx] /= fmaxf(d_cnt[idx >> 5], 1.f);
}

__global__ void deg_kernel() {
    int idx = blockIdx.x * blockDim.x + threadIdx.x;
    if (idx >= ET) return;
    int dst = (idx < EE) ? d_edst[idx] : (idx - EE);
    atomicAdd(&d_deg[dst], 1);
}

// single-block exclusive scan over degrees -> rowptr & cursor
__global__ void scan_kernel() {
    __shared__ int warpsum[32];
    __shared__ int s_carry;
    int t = threadIdx.x;
    if (t == 0) s_carry = 0;
    __syncthreads();
    for (int base = 0; base < NN; base += 1024) {
        int i = base + t;
        int v = (i < NN) ? d_deg[i] : 0;
        int lane = t & 31, w = t >> 5;
        int x = v;
        #pragma unroll
        for (int o = 1; o < 32; o <<= 1) {
            int y = __shfl_up_sync(0xffffffffu, x, o);
            if (lane >= o) x += y;
        }
        if (lane == 31) warpsum[w] = x;
        __syncthreads();
        if (w == 0) {
            int s = warpsum[lane];
            #pragma unroll
            for (int o = 1; o < 32; o <<= 1) {
                int y = __shfl_up_sync(0xffffffffu, s, o);
                if (lane >= o) s += y;
            }
            warpsum[lane] = s;
        }
        __syncthreads();
        int incl = x + (w > 0 ? warpsum[w - 1] : 0);
        int excl = incl - v;
        int carry = s_carry;
        if (i < NN) {
            d_rowptr[i] = carry + excl;
            d_cursor[i] = carry + excl;
        }
        __syncthreads();
        if (t == 1023) s_carry = carry + incl;
        __syncthreads();
    }
    if (t == 0) d_rowptr[NN] = s_carry;
}

__global__ void scatter_kernel() {
    int idx = blockIdx.x * blockDim.x + threadIdx.x;
    if (idx >= ET) return;
    int src, dst;
    if (idx < EE) { src = d_esrc[idx]; dst = d_edst[idx]; }
    else          { src = dst = idx - EE; }
    int p = atomicAdd(&d_cursor[dst], 1);
    d_csr_src[p] = src;
    d_csr_eid[p] = idx;
}

// V_e[k,h] = sum_c W_e1[k, h*32+c] * att_e[h,c]
__global__ void ve_kernel(const float* __restrict__ We,
                          const float* __restrict__ atte) {
    int t = threadIdx.x;          // 384 threads = 32k x 12h
    int k = t / HH, h = t - HH * (t / HH);
    float s = 0.f;
    #pragma unroll
    for (int c = 0; c < CC; c++)
        s = fmaf(We[k * HC + h * CC + c], atte[h * CC + c], s);
    d_Ve[k * HH + h] = s;
}

// a_e[e,h] = edge_attr_full[e,:] @ V_e[:,h]
__global__ void ae_kernel(const float* __restrict__ ea) {
    __shared__ float sVe[CC * HH];
    int tid = threadIdx.x;
    for (int i = tid; i < CC * HH; i += 256) sVe[i] = d_Ve[i];
    __syncthreads();
    int idx = blockIdx.x * 256 + tid;
    if (idx >= ET * HH) return;
    int e = idx / HH, hh = idx - HH * e;
    const float* row = (e < EE) ? (ea + (size_t)e * CC)
                                : (d_loop_attr + (size_t)(e - EE) * CC);
    float s = 0.f;
    #pragma unroll
    for (int k = 0; k < CC; k++) s = fmaf(row[k], sVe[k * HH + hh], s);
    d_ae[idx] = s;
}

// ---------------- SGEMM (fp32 SIMT, 128x128x8, 8x8 per thread) ---------------
// C[M,Nn] = A[M,K] @ B[K,Nn].  Requires K%8==0, Nn%128==0.
// which: 0 -> A = ext (x), C = d_hx1 ; 1 -> A = d_h1, C = d_hx2
__global__ void __launch_bounds__(256) sgemm_kernel(
    int which, const float* __restrict__ Aext, const float* __restrict__ B,
    int M, int Nn, int K) {
    const float* A = (which == 0) ? Aext : d_h1;
    float* Cm      = (which == 0) ? d_hx1 : d_hx2;

    __shared__ float As[8][128];
    __shared__ float Bs[8][128];
    int tid  = threadIdx.x;
    int trow = tid / 16;          // 0..15
    int tcol = tid % 16;          // 0..15
    int bm = blockIdx.y * 128;
    int bn = blockIdx.x * 128;

    int am = tid / 2, ak = (tid % 2) * 4;       // A: 128 rows x 8 k
    int bkr = tid / 32, bnc = (tid % 32) * 4;   // B: 8 k x 128 n

    float acc[8][8];
    #pragma unroll
    for (int i = 0; i < 8; i++)
        #pragma unroll
        for (int j = 0; j < 8; j++) acc[i][j] = 0.f;

    for (int k0 = 0; k0 < K; k0 += 8) {
        float4 av;
        if (bm + am < M)
            av = *reinterpret_cast<const float4*>(A + (size_t)(bm + am) * K + k0 + ak);
        else
            av = make_float4(0.f, 0.f, 0.f, 0.f);
        As[ak + 0][am] = av.x; As[ak + 1][am] = av.y;
        As[ak + 2][am] = av.z; As[ak + 3][am] = av.w;
        float4 bv = *reinterpret_cast<const float4*>(B + (size_t)(k0 + bkr) * Nn + bn + bnc);
        *reinterpret_cast<float4*>(&Bs[bkr][bnc]) = bv;
        __syncthreads();
        #pragma unroll
        for (int kk = 0; kk < 8; kk++) {
            float a[8], b[8];
            #pragma unroll
            for (int i = 0; i < 8; i += 4) {
                float4 t4 = *reinterpret_cast<const float4*>(&As[kk][trow * 8 + i]);
                a[i] = t4.x; a[i + 1] = t4.y; a[i + 2] = t4.z; a[i + 3] = t4.w;
            }
            #pragma unroll
            for (int j = 0; j < 8; j += 4) {
                float4 t4 = *reinterpret_cast<const float4*>(&Bs[kk][tcol * 8 + j]);
                b[j] = t4.x; b[j + 1] = t4.y; b[j + 2] = t4.z; b[j + 3] = t4.w;
            }
            #pragma unroll
            for (int i = 0; i < 8; i++)
                #pragma unroll
                for (int j = 0; j < 8; j++)
                    acc[i][j] = fmaf(a[i], b[j], acc[i][j]);
        }
        __syncthreads();
    }
    #pragma unroll
    for (int i = 0; i < 8; i++) {
        int row = bm + trow * 8 + i;
        if (row < M) {
            #pragma unroll
            for (int j = 0; j < 8; j += 4) {
                float4 v = make_float4(acc[i][j], acc[i][j + 1], acc[i][j + 2], acc[i][j + 3]);
                *reinterpret_cast<float4*>(Cm + (size_t)row * Nn + bn + tcol * 8 + j) = v;
            }
        }
    }
}

// per-node attention dots: a_s[n,h] = <hx[n,h,:], att_src[h,:]>, same for dst
__global__ void dots_kernel(int which, const float* __restrict__ attS,
                            const float* __restrict__ attD) {
    const float* hx = (which == 0) ? d_hx1 : d_hx2;
    float* as_o = (which == 0) ? d_as1 : d_as2;
    float* ad_o = (which == 0) ? d_ad1 : d_ad2;
    int n = blockIdx.x, t = threadIdx.x;
    float v = hx[(size_t)n * HC + t];
    float s = v * attS[t];
    float d = v * attD[t];
    #pragma unroll
    for (int o = 16; o > 0; o >>= 1) {
        s += __shfl_xor_sync(0xffffffffu, s, o);
        d += __shfl_xor_sync(0xffffffffu, d, o);
    }
    if ((t & 31) == 0) {
        int h = t >> 5;
        as_o[n * HH + h] = s;
        ad_o[n * HH + h] = d;
    }
}

// ---------------- layer-1 aggregation (with edge attention, ELU epilogue) ----
__global__ void __launch_bounds__(HC) agg1_kernel(const float* __restrict__ b1) {
    int n = blockIdx.x;
    int t = threadIdx.x;
    int h = t >> 5;
    __shared__ float    s_ad[HH];
    __shared__ unsigned s_mu[HH];
    __shared__ float    s_mf[HH], s_den[HH], s_inv[HH];
    __shared__ int      s_src[CHUNK];
    __shared__ float    s_alpha[CHUNK * HH];

    int beg = d_rowptr[n], end = d_rowptr[n + 1];
    int deg = end - beg;
    if (t < HH) { s_ad[t] = d_ad1[n * HH + t]; s_mu[t] = 0u; s_den[t] = 0.f; }
    __syncthreads();

    for (int idx = t; idx < deg * HH; idx += HC) {
        int j = idx / HH, hh = idx - HH * j;
        int p = beg + j;
        int src = d_csr_src[p], eid = d_csr_eid[p];
        float e = d_as1[src * HH + hh] + s_ad[hh] + d_ae[(size_t)eid * HH + hh];
        e = (e > 0.f) ? e : NEG_SLOPE * e;
        atomicMax(&s_mu[hh], enc_f(e));
    }
    __syncthreads();
    if (t < HH) s_mf[t] = dec_f(s_mu[t]);
    __syncthreads();
    for (int idx = t; idx < deg * HH; idx += HC) {
        int j = idx / HH, hh = idx - HH * j;
        int p = beg + j;
        int src = d_csr_src[p], eid = d_csr_eid[p];
        float e = d_as1[src * HH + hh] + s_ad[hh] + d_ae[(size_t)eid * HH + hh];
        e = (e > 0.f) ? e : NEG_SLOPE * e;
        atomicAdd(&s_den[hh], __expf(e - s_mf[hh]));
    }
    __syncthreads();
    if (t < HH) s_inv[t] = 1.f / s_den[t];
    __syncthreads();

    float acc = 0.f;
    for (int base = 0; base < deg; base += CHUNK) {
        int cn = min(CHUNK, deg - base);
        for (int idx = t; idx < cn * HH; idx += HC) {
            int j = idx / HH, hh = idx - HH * j;
            int p = beg + base + j;
            int src = d_csr_src[p], eid = d_csr_eid[p];
            float e = d_as1[src * HH + hh] + s_ad[hh] + d_ae[(size_t)eid * HH + hh];
            e = (e > 0.f) ? e : NEG_SLOPE * e;
            s_alpha[j * HH + hh] = __expf(e - s_mf[hh]) * s_inv[hh];
            if (hh == 0) s_src[j] = src;
        }
        __syncthreads();
        #pragma unroll 4
        for (int j = 0; j < cn; j++)
            acc = fmaf(s_alpha[j * HH + h], d_hx1[(size_t)s_src[j] * HC + t], acc);
        __syncthreads();
    }
    float v = acc + b1[t];
    d_h1[(size_t)n * HC + t] = (v > 0.f) ? v : expm1f(v);
}

// ---------------- layer-2 aggregation (mean over heads + log_softmax) --------
__global__ void __launch_bounds__(HC) agg2_kernel(const float* __restrict__ b2,
                                                  float* __restrict__ out,
                                                  int out_size) {
    int n = blockIdx.x;
    int t = threadIdx.x;
    int h = t >> 5;
    __shared__ float    s_ad[HH];
    __shared__ unsigned s_mu[HH];
    __shared__ float    s_mf[HH], s_den[HH], s_inv[HH];
    __shared__ int      s_src[CHUNK];
    __shared__ float    s_alpha[CHUNK * HH];
    __shared__ float    s_out[HC];

    int beg = d_rowptr[n], end = d_rowptr[n + 1];
    int deg = end - beg;
    if (t < HH) { s_ad[t] = d_ad2[n * HH + t]; s_mu[t] = 0u; s_den[t] = 0.f; }
    __syncthreads();

    for (int idx = t; idx < deg * HH; idx += HC) {
        int j = idx / HH, hh = idx - HH * j;
        int src = d_csr_src[beg + j];
        float e = d_as2[src * HH + hh] + s_ad[hh];
        e = (e > 0.f) ? e : NEG_SLOPE * e;
        atomicMax(&s_mu[hh], enc_f(e));
    }
    __syncthreads();
    if (t < HH) s_mf[t] = dec_f(s_mu[t]);
    __syncthreads();
    for (int idx = t; idx < deg * HH; idx += HC) {
        int j = idx / HH, hh = idx - HH * j;
        int src = d_csr_src[beg + j];
        float e = d_as2[src * HH + hh] + s_ad[hh];
        e = (e > 0.f) ? e : NEG_SLOPE * e;
        atomicAdd(&s_den[hh], __expf(e - s_mf[hh]));
    }
    __syncthreads();
    if (t < HH) s_inv[t] = 1.f / s_den[t];
    __syncthreads();

    float acc = 0.f;
    for (int base = 0; base < deg; base += CHUNK) {
        int cn = min(CHUNK, deg - base);
        for (int idx = t; idx < cn * HH; idx += HC) {
            int j = idx / HH, hh = idx - HH * j;
            int src = d_csr_src[beg + base + j];
            float e = d_as2[src * HH + hh] + s_ad[hh];
            e = (e > 0.f) ? e : NEG_SLOPE * e;
            s_alpha[j * HH + hh] = __expf(e - s_mf[hh]) * s_inv[hh];
            if (hh == 0) s_src[j] = src;
        }
        __syncthreads();
        #pragma unroll 4
        for (int j = 0; j < cn; j++)
            acc = fmaf(s_alpha[j * HH + h], d_hx2[(size_t)s_src[j] * HC + t], acc);
        __syncthreads();
    }
    s_out[t] = acc;
    __syncthreads();
    if (t < CC) {
        float s = 0.f;
        #pragma unroll
        for (int hh = 0; hh < HH; hh++) s += s_out[hh * CC + t];
        float val = s * (1.f / (float)HH) + b2[t];
        // log_softmax over the 32 classes (threads 0..31 = warp 0, all active)
        float m = val;
        #pragma unroll
        for (int o = 16; o > 0; o >>= 1)
            m = fmaxf(m, __shfl_xor_sync(0xffffffffu, m, o));
        float ex = __expf(val - m);
        float ssum = ex;
        #pragma unroll
        for (int o = 16; o > 0; o >>= 1)
            ssum += __shfl_xor_sync(0xffffffffu, ssum, o);
        float lse = m + logf(ssum);
        int i0 = n * CC + t;
        if (i0 < out_size) out[i0] = val;                 // h2
        int i1 = NN * CC + i0;
        if (i1 < out_size) out[i1] = val - lse;           // log_softmax(h2)
    }
}

// ---------------- launch -----------------------------------------------------
extern "C" void kernel_launch(void* const* d_in, const int* in_sizes, int n_in,
                              void* d_out, int out_size) {
    const float*     x      = (const float*)d_in[0];
    const int*       ei32   = (const int*)d_in[1];   // int32 or int64 (probed)
    const float*     ea     = (const float*)d_in[2];
    const float*     W1     = (const float*)d_in[3];
    const float*     attS1  = (const float*)d_in[4];
    const float*     attD1  = (const float*)d_in[5];
    const float*     We1    = (const float*)d_in[6];
    const float*     attE1  = (const float*)d_in[7];
    const float*     b1     = (const float*)d_in[8];
    const float*     W2     = (const float*)d_in[9];
    const float*     attS2  = (const float*)d_in[10];
    const float*     attD2  = (const float*)d_in[11];
    const float*     b2     = (const float*)d_in[12];
    float* out = (float*)d_out;

    // --- edge-index dtype probe + conversion to flat int32 ---
    detect_kernel<<<1, 32>>>(ei32);
    convert_kernel<<<(EE + 255) / 256, 256>>>(ei32);

    // --- preprocessing: self-loop attrs + CSR by destination ---
    init_kernel<<<256, 256>>>();
    edge_sums_kernel<<<(EE * CC + 255) / 256, 256>>>(ea);
    loop_div_kernel<<<(NN * CC + 255) / 256, 256>>>();
    deg_kernel<<<(ET + 255) / 256, 256>>>();
    scan_kernel<<<1, 1024>>>();
    scatter_kernel<<<(ET + 255) / 256, 256>>>();

    // --- edge attention scalars (folded W_e1 @ att_edge1) ---
    ve_kernel<<<1, HC>>>(We1, attE1);
    ae_kernel<<<(ET * HH + 255) / 256, 256>>>(ea);

    // --- layer 1 ---
    sgemm_kernel<<<dim3(HC / 128, (NN + 127) / 128), 256>>>(0, x, W1, NN, HC, FIN);
    dots_kernel<<<NN, HC>>>(0, attS1, attD1);
    agg1_kernel<<<NN, HC>>>(b1);

    // --- layer 2 ---
    sgemm_kernel<<<dim3(HC / 128, (NN + 127) / 128), 256>>>(1, nullptr, W2, NN, HC, HC);
    dots_kernel<<<NN, HC>>>(1, attS2, attD2);
    agg2_kernel<<<NN, HC>>>(b2, out, out_size);
}

// round 8
// speedup vs baseline: 1.1823x; 1.1823x over previous
#include <cuda_runtime.h>
#include <cuda_bf16.h>
#include <math.h>
#include <stdint.h>

// Problem constants (shapes fixed by dataset).
#define NN    25000
#define NPAD  25088          // 196*128, padded row count for MMA tiles
#define EE    400000
#define ET    (EE + NN)
#define FIN   256
#define CC    32
#define HH    12
#define HC    384
#define NEG_SLOPE 0.2f
#define CHUNK 64

// ---------------- scratch (static device globals; allocation-free) ----------
__device__ __align__(16) __nv_bfloat16 d_xb[(size_t)NPAD * FIN];   // zero-padded tail
__device__ __align__(16) __nv_bfloat16 d_xs[(size_t)NPAD * FIN];
__device__ __align__(16) __nv_bfloat16 d_h1b[(size_t)NPAD * HC];
__device__ __align__(16) __nv_bfloat16 d_h1s[(size_t)NPAD * HC];
__device__ __align__(16) __nv_bfloat16 d_w1b[(size_t)HC * FIN];
__device__ __align__(16) __nv_bfloat16 d_w1s[(size_t)HC * FIN];
__device__ __align__(16) __nv_bfloat16 d_w2b[(size_t)HC * HC];
__device__ __align__(16) __nv_bfloat16 d_w2s[(size_t)HC * HC];
__device__ __align__(16) float d_hx1[(size_t)NN * HC];
__device__ __align__(16) float d_hx2[(size_t)NN * HC];
__device__ float d_as1[NN * HH], d_ad1[NN * HH];
__device__ float d_as2[NN * HH], d_ad2[NN * HH];
__device__ float d_loop_attr[(size_t)NN * CC];
__device__ float d_Ve[CC * HH];
__device__ float d_ae[(size_t)ET * HH];
__device__ int   d_deg[NN];
__device__ int   d_rowptr[NN + 1];
__device__ int   d_cursor[NN];
__device__ int   d_csr_src[ET];
__device__ int   d_csr_eid[ET];
__device__ int   d_esrc[EE];
__device__ int   d_edst[EE];
__device__ int   d_is64;

// ---------------- float-ordered-uint helpers for shared atomicMax ------------
__device__ __forceinline__ unsigned enc_f(float f) {
    unsigned u = __float_as_uint(f);
    return (u & 0x80000000u) ? ~u : (u | 0x80000000u);
}
__device__ __forceinline__ float dec_f(unsigned k) {
    return (k & 0x80000000u) ? __uint_as_float(k & 0x7FFFFFFFu)
                             : __uint_as_float(~k);
}

// ---------------- edge-index dtype probe + conversion ------------------------
__global__ void detect_kernel(const int* __restrict__ ei32) {
    if (threadIdx.x == 0) {
        int z = 1;
        #pragma unroll
        for (int i = 1; i < 64; i += 2) z &= (ei32[i] == 0);
        d_is64 = z;
    }
}
__global__ void convert_kernel(const int* __restrict__ ei32) {
    int e = blockIdx.x * blockDim.x + threadIdx.x;
    if (e >= EE) return;
    if (d_is64) {
        d_esrc[e] = ei32[2 * (size_t)e];
        d_edst[e] = ei32[2 * ((size_t)EE + e)];
    } else {
        d_esrc[e] = ei32[e];
        d_edst[e] = ei32[EE + e];
    }
}

// ---------------- preprocessing ----------------------------------------------
__global__ void zero_deg_kernel() {
    int i = blockIdx.x * blockDim.x + threadIdx.x;
    if (i < NN) d_deg[i] = 0;
}
__global__ void deg_kernel() {
    int idx = blockIdx.x * blockDim.x + threadIdx.x;
    if (idx >= ET) return;
    int dst = (idx < EE) ? d_edst[idx] : (idx - EE);
    atomicAdd(&d_deg[dst], 1);
}
__global__ void scan_kernel() {
    __shared__ int warpsum[32];
    __shared__ int s_carry;
    int t = threadIdx.x;
    if (t == 0) s_carry = 0;
    __syncthreads();
    for (int base = 0; base < NN; base += 1024) {
        int i = base + t;
        int v = (i < NN) ? d_deg[i] : 0;
        int lane = t & 31, w = t >> 5;
        int x = v;
        #pragma unroll
        for (int o = 1; o < 32; o <<= 1) {
            int y = __shfl_up_sync(0xffffffffu, x, o);
            if (lane >= o) x += y;
        }
        if (lane == 31) warpsum[w] = x;
        __syncthreads();
        if (w == 0) {
            int s = warpsum[lane];
            #pragma unroll
            for (int o = 1; o < 32; o <<= 1) {
                int y = __shfl_up_sync(0xffffffffu, s, o);
                if (lane >= o) s += y;
            }
            warpsum[lane] = s;
        }
        __syncthreads();
        int incl = x + (w > 0 ? warpsum[w - 1] : 0);
        int excl = incl - v;
        int carry = s_carry;
        if (i < NN) { d_rowptr[i] = carry + excl; d_cursor[i] = carry + excl; }
        __syncthreads();
        if (t == 1023) s_carry = carry + incl;
        __syncthreads();
    }
    if (t == 0) d_rowptr[NN] = s_carry;
}
__global__ void scatter_kernel() {
    int idx = blockIdx.x * blockDim.x + threadIdx.x;
    if (idx >= ET) return;
    int src, dst;
    if (idx < EE) { src = d_esrc[idx]; dst = d_edst[idx]; }
    else          { src = dst = idx - EE; }
    int p = atomicAdd(&d_cursor[dst], 1);
    d_csr_src[p] = src;
    d_csr_eid[p] = idx;
}

// PyG add_self_loops fill_value='mean': per-dst mean of incoming edge_attr
// (gather over CSR; warp per node, lane = feature)
__global__ void loop_mean_kernel(const float* __restrict__ ea) {
    int n = blockIdx.x * 8 + (threadIdx.x >> 5);
    if (n >= NN) return;
    int lane = threadIdx.x & 31;
    int beg = d_rowptr[n], end = d_rowptr[n + 1];
    float s = 0.f;
    for (int p = beg; p < end; p++) {
        int eid = d_csr_eid[p];
        if (eid < EE) s += ea[(size_t)eid * CC + lane];
    }
    float cnt = (float)(end - beg - 1);   // self-loop excluded
    d_loop_attr[n * CC + lane] = s / fmaxf(cnt, 1.f);
}

// V_e[k,h] = sum_c W_e1[k, h*32+c] * att_e[h,c]
__global__ void ve_kernel(const float* __restrict__ We,
                          const float* __restrict__ atte) {
    int t = threadIdx.x;          // 384 = 32k x 12h
    int k = t / HH, h = t - HH * (t / HH);
    float s = 0.f;
    #pragma unroll
    for (int c = 0; c < CC; c++)
        s = fmaf(We[k * HC + h * CC + c], atte[h * CC + c], s);
    d_Ve[k * HH + h] = s;
}

// a_e[e,h] = edge_attr_full[e,:] @ V_e[:,h]
__global__ void ae_kernel(const float* __restrict__ ea) {
    __shared__ float sVe[CC * HH];
    int tid = threadIdx.x;
    for (int i = tid; i < CC * HH; i += 256) sVe[i] = d_Ve[i];
    __syncthreads();
    int idx = blockIdx.x * 256 + tid;
    if (idx >= ET * HH) return;
    int e = idx / HH, hh = idx - HH * e;
    const float* row = (e < EE) ? (ea + (size_t)e * CC)
                                : (d_loop_attr + (size_t)(e - EE) * CC);
    float s = 0.f;
    #pragma unroll
    for (int k = 0; k < CC; k++) s = fmaf(row[k], sVe[k * HH + hh], s);
    d_ae[idx] = s;
}

// ---------------- fp32 -> bf16 big/small split conversions --------------------
__global__ void convx_kernel(const float* __restrict__ x) {
    int idx = blockIdx.x * blockDim.x + threadIdx.x;
    if (idx >= NN * FIN) return;
    float v = x[idx];
    __nv_bfloat16 b = __float2bfloat16(v);
    d_xb[idx] = b;
    d_xs[idx] = __float2bfloat16(v - __bfloat162float(b));
}
// W [K, HC] -> W^T pairs [HC][K] (K-major rows = col-major B for mma row.col)
__global__ void wt_kernel(int which, const float* __restrict__ W) {
    int K = which ? HC : FIN;
    __nv_bfloat16* wb = which ? d_w2b : d_w1b;
    __nv_bfloat16* ws = which ? d_w2s : d_w1s;
    int idx = blockIdx.x * blockDim.x + threadIdx.x;
    if (idx >= K * HC) return;
    int k = idx / HC, n = idx - HC * (idx / HC);
    float v = W[idx];
    __nv_bfloat16 b = __float2bfloat16(v);
    wb[(size_t)n * K + k] = b;
    ws[(size_t)n * K + k] = __float2bfloat16(v - __bfloat162float(b));
}

// ---------------- bf16 mma.sync GEMM (3x split), 128x128 tile, 8 warps -------
// C = A @ B^T with A [M,K] row-major bf16 pairs, B^T [N,K] row-major bf16 pairs.
// Runs on baseline-PTX tensor path (m16n8k16 HMMA) - no sm_103a features.
#define BM 128
#define BN 128
#define BKK 64
#define ASTR 72            // padded smem row stride (elements) -> conflict-free frags
#define TILE_B (128 * ASTR * 2)
#define GEMM_SMEM (4 * TILE_B)   // 73728 bytes

__device__ __forceinline__ void mma16816(float* c, const uint32_t* a,
                                         const uint32_t* b) {
    asm volatile(
        "mma.sync.aligned.m16n8k16.row.col.f32.bf16.bf16.f32 "
        "{%0,%1,%2,%3}, {%4,%5,%6,%7}, {%8,%9}, {%0,%1,%2,%3};\n"
        : "+f"(c[0]), "+f"(c[1]), "+f"(c[2]), "+f"(c[3])
        : "r"(a[0]), "r"(a[1]), "r"(a[2]), "r"(a[3]), "r"(b[0]), "r"(b[1]));
}

__global__ void __launch_bounds__(256) gemm_kernel(int which) {
    extern __shared__ char smem[];
    __nv_bfloat16* sAb = (__nv_bfloat16*)(smem);
    __nv_bfloat16* sAs = (__nv_bfloat16*)(smem + TILE_B);
    __nv_bfloat16* sBb = (__nv_bfloat16*)(smem + 2 * TILE_B);
    __nv_bfloat16* sBs = (__nv_bfloat16*)(smem + 3 * TILE_B);

    const int Kt = which ? HC : FIN;
    const __nv_bfloat16* Ab  = which ? d_h1b : d_xb;
    const __nv_bfloat16* As_ = which ? d_h1s : d_xs;
    const __nv_bfloat16* Bb  = which ? d_w2b : d_w1b;
    const __nv_bfloat16* Bs  = which ? d_w2s : d_w1s;
    float* Cm = which ? d_hx2 : d_hx1;

    int tid = threadIdx.x;
    int wid = tid >> 5, lane = tid & 31;
    int wm = (wid & 3) * 32;     // warp m offset within tile
    int wn = (wid >> 2) * 64;    // warp n offset within tile
    int tq = lane >> 2, tr = lane & 3;

    int bm = blockIdx.y * BM;
    int bn = blockIdx.x * BN;

    float acc[2][8][4];
    #pragma unroll
    for (int mt = 0; mt < 2; mt++)
        #pragma unroll
        for (int nt = 0; nt < 8; nt++)
            #pragma unroll
            for (int q = 0; q < 4; q++) acc[mt][nt][q] = 0.f;

    int lrow = tid >> 1;           // 0..127
    int lcol = (tid & 1) * 32;     // half-row of 32 bf16 = 4x uint4

    for (int k0 = 0; k0 < Kt; k0 += BKK) {
        const uint4* gab = (const uint4*)(Ab  + (size_t)(bm + lrow) * Kt + k0 + lcol);
        const uint4* gas = (const uint4*)(As_ + (size_t)(bm + lrow) * Kt + k0 + lcol);
        const uint4* gbb = (const uint4*)(Bb  + (size_t)(bn + lrow) * Kt + k0 + lcol);
        const uint4* gbs = (const uint4*)(Bs  + (size_t)(bn + lrow) * Kt + k0 + lcol);
        uint4* pab = (uint4*)&sAb[lrow * ASTR + lcol];
        uint4* pas = (uint4*)&sAs[lrow * ASTR + lcol];
        uint4* pbb = (uint4*)&sBb[lrow * ASTR + lcol];
        uint4* pbs = (uint4*)&sBs[lrow * ASTR + lcol];
        #pragma unroll
        for (int i = 0; i < 4; i++) {
            pab[i] = gab[i];
            pas[i] = gas[i];
            pbb[i] = gbb[i];
            pbs[i] = gbs[i];
        }
        __syncthreads();
        #pragma unroll
        for (int s = 0; s < BKK / 16; s++) {
            int kk = s * 16 + tr * 2;
            uint32_t afb[2][4], afs[2][4];
            #pragma unroll
            for (int mt = 0; mt < 2; mt++) {
                int r0 = wm + mt * 16 + tq;
                afb[mt][0] = *(const uint32_t*)&sAb[r0 * ASTR + kk];
                afb[mt][1] = *(const uint32_t*)&sAb[(r0 + 8) * ASTR + kk];
                afb[mt][2] = *(const uint32_t*)&sAb[r0 * ASTR + kk + 8];
                afb[mt][3] = *(const uint32_t*)&sAb[(r0 + 8) * ASTR + kk + 8];
                afs[mt][0] = *(const uint32_t*)&sAs[r0 * ASTR + kk];
                afs[mt][1] = *(const uint32_t*)&sAs[(r0 + 8) * ASTR + kk];
                afs[mt][2] = *(const uint32_t*)&sAs[r0 * ASTR + kk + 8];
                afs[mt][3] = *(const uint32_t*)&sAs[(r0 + 8) * ASTR + kk + 8];
            }
            #pragma unroll
            for (int nt = 0; nt < 8; nt++) {
                int nr = wn + nt * 8 + tq;
                uint32_t bfb[2], bfs[2];
                bfb[0] = *(const uint32_t*)&sBb[nr * ASTR + kk];
                bfb[1] = *(const uint32_t*)&sBb[nr * ASTR + kk + 8];
                bfs[0] = *(const uint32_t*)&sBs[nr * ASTR + kk];
                bfs[1] = *(const uint32_t*)&sBs[nr * ASTR + kk + 8];
                #pragma unroll
                for (int mt = 0; mt < 2; mt++) {
                    mma16816(acc[mt][nt], afb[mt], bfb);   // big  * big
                    mma16816(acc[mt][nt], afb[mt], bfs);   // big  * small
                    mma16816(acc[mt][nt], afs[mt], bfb);   // small* big
                }
            }
        }
        __syncthreads();
    }
    // epilogue: c0,c1 -> (row tq, cols 2tr..+1); c2,c3 -> row tq+8
    #pragma unroll
    for (int mt = 0; mt < 2; mt++) {
        int r0 = bm + wm + mt * 16 + tq;
        #pragma unroll
        for (int nt = 0; nt < 8; nt++) {
            int c0 = bn + wn + nt * 8 + tr * 2;
            if (r0 < NN)
                *(float2*)&Cm[(size_t)r0 * HC + c0] =
                    make_float2(acc[mt][nt][0], acc[mt][nt][1]);
            if (r0 + 8 < NN)
                *(float2*)&Cm[(size_t)(r0 + 8) * HC + c0] =
                    make_float2(acc[mt][nt][2], acc[mt][nt][3]);
        }
    }
}

// per-node attention dots: a_s[n,h] = <hx[n,h,:], att_src[h,:]>, same for dst
__global__ void dots_kernel(int which, const float* __restrict__ attS,
                            const float* __restrict__ attD) {
    const float* hx = (which == 0) ? d_hx1 : d_hx2;
    float* as_o = (which == 0) ? d_as1 : d_as2;
    float* ad_o = (which == 0) ? d_ad1 : d_ad2;
    int n = blockIdx.x, t = threadIdx.x;
    float v = hx[(size_t)n * HC + t];
    float s = v * attS[t];
    float d = v * attD[t];
    #pragma unroll
    for (int o = 16; o > 0; o >>= 1) {
        s += __shfl_xor_sync(0xffffffffu, s, o);
        d += __shfl_xor_sync(0xffffffffu, d, o);
    }
    if ((t & 31) == 0) {
        int h = t >> 5;
        as_o[n * HH + h] = s;
        ad_o[n * HH + h] = d;
    }
}

// ---------------- layer-1 aggregation (edge attention, ELU, bf16-split out) --
__global__ void __launch_bounds__(HC) agg1_kernel(const float* __restrict__ b1) {
    int n = blockIdx.x;
    int t = threadIdx.x;
    int h = t >> 5;
    __shared__ float    s_ad[HH];
    __shared__ unsigned s_mu[HH];
    __shared__ float    s_mf[HH], s_den[HH], s_inv[HH];
    __shared__ int      s_src[CHUNK];
    __shared__ float    s_alpha[CHUNK * HH];

    int beg = d_rowptr[n], end = d_rowptr[n + 1];
    int deg = end - beg;
    if (t < HH) { s_ad[t] = d_ad1[n * HH + t]; s_mu[t] = 0u; s_den[t] = 0.f; }
    __syncthreads();

    for (int idx = t; idx < deg * HH; idx += HC) {
        int j = idx / HH, hh = idx - HH * j;
        int p = beg + j;
        int src = d_csr_src[p], eid = d_csr_eid[p];
        float e = d_as1[src * HH + hh] + s_ad[hh] + d_ae[(size_t)eid * HH + hh];
        e = (e > 0.f) ? e : NEG_SLOPE * e;
        atomicMax(&s_mu[hh], enc_f(e));
    }
    __syncthreads();
    if (t < HH) s_mf[t] = dec_f(s_mu[t]);
    __syncthreads();
    for (int idx = t; idx < deg * HH; idx += HC) {
        int j = idx / HH, hh = idx - HH * j;
        int p = beg + j;
        int src = d_csr_src[p], eid = d_csr_eid[p];
        float e = d_as1[src * HH + hh] + s_ad[hh] + d_ae[(size_t)eid * HH + hh];
        e = (e > 0.f) ? e : NEG_SLOPE * e;
        atomicAdd(&s_den[hh], __expf(e - s_mf[hh]));
    }
    __syncthreads();
    if (t < HH) s_inv[t] = 1.f / s_den[t];
    __syncthreads();

    float acc = 0.f;
    for (int base = 0; base < deg; base += CHUNK) {
        int cn = min(CHUNK, deg - base);
        for (int idx = t; idx < cn * HH; idx += HC) {
            int j = idx / HH, hh = idx - HH * j;
            int p = beg + base + j;
            int src = d_csr_src[p], eid = d_csr_eid[p];
            float e = d_as1[src * HH + hh] + s_ad[hh] + d_ae[(size_t)eid * HH + hh];
            e = (e > 0.f) ? e : NEG_SLOPE * e;
            s_alpha[j * HH + hh] = __expf(e - s_mf[hh]) * s_inv[hh];
            if (hh == 0) s_src[j] = src;
        }
        __syncthreads();
        #pragma unroll 4
        for (int j = 0; j < cn; j++)
            acc = fmaf(s_alpha[j * HH + h], d_hx1[(size_t)s_src[j] * HC + t], acc);
        __syncthreads();
    }
    float v = acc + b1[t];
    v = (v > 0.f) ? v : expm1f(v);                 // ELU
    __nv_bfloat16 big = __float2bfloat16(v);       // bf16 split for gemm2
    d_h1b[(size_t)n * HC + t] = big;
    d_h1s[(size_t)n * HC + t] = __float2bfloat16(v - __bfloat162float(big));
}

// ---------------- layer-2 aggregation (mean over heads + log_softmax) --------
__global__ void __launch_bounds__(HC) agg2_kernel(const float* __restrict__ b2,
                                                  float* __restrict__ out,
                                                  int out_size) {
    int n = blockIdx.x;
    int t = threadIdx.x;
    int h = t >> 5;
    __shared__ float    s_ad[HH];
    __shared__ unsigned s_mu[HH];
    __shared__ float    s_mf[HH], s_den[HH], s_inv[HH];
    __shared__ int      s_src[CHUNK];
    __shared__ float    s_alpha[CHUNK * HH];
    __shared__ float    s_out[HC];

    int beg = d_rowptr[n], end = d_rowptr[n + 1];
    int deg = end - beg;
    if (t < HH) { s_ad[t] = d_ad2[n * HH + t]; s_mu[t] = 0u; s_den[t] = 0.f; }
    __syncthreads();

    for (int idx = t; idx < deg * HH; idx += HC) {
        int j = idx / HH, hh = idx - HH * j;
        int src = d_csr_src[beg + j];
        float e = d_as2[src * HH + hh] + s_ad[hh];
        e = (e > 0.f) ? e : NEG_SLOPE * e;
        atomicMax(&s_mu[hh], enc_f(e));
    }
    __syncthreads();
    if (t < HH) s_mf[t] = dec_f(s_mu[t]);
    __syncthreads();
    for (int idx = t; idx < deg * HH; idx += HC) {
        int j = idx / HH, hh = idx - HH * j;
        int src = d_csr_src[beg + j];
        float e = d_as2[src * HH + hh] + s_ad[hh];
        e = (e > 0.f) ? e : NEG_SLOPE * e;
        atomicAdd(&s_den[hh], __expf(e - s_mf[hh]));
    }
    __syncthreads();
    if (t < HH) s_inv[t] = 1.f / s_den[t];
    __syncthreads();

    float acc = 0.f;
    for (int base = 0; base < deg; base += CHUNK) {
        int cn = min(CHUNK, deg - base);
        for (int idx = t; idx < cn * HH; idx += HC) {
            int j = idx / HH, hh = idx - HH * j;
            int src = d_csr_src[beg + base + j];
            float e = d_as2[src * HH + hh] + s_ad[hh];
            e = (e > 0.f) ? e : NEG_SLOPE * e;
            s_alpha[j * HH + hh] = __expf(e - s_mf[hh]) * s_inv[hh];
            if (hh == 0) s_src[j] = src;
        }
        __syncthreads();
        #pragma unroll 4
        for (int j = 0; j < cn; j++)
            acc = fmaf(s_alpha[j * HH + h], d_hx2[(size_t)s_src[j] * HC + t], acc);
        __syncthreads();
    }
    s_out[t] = acc;
    __syncthreads();
    if (t < CC) {
        float s = 0.f;
        #pragma unroll
        for (int hh = 0; hh < HH; hh++) s += s_out[hh * CC + t];
        float val = s * (1.f / (float)HH) + b2[t];
        float m = val;
        #pragma unroll
        for (int o = 16; o > 0; o >>= 1)
            m = fmaxf(m, __shfl_xor_sync(0xffffffffu, m, o));
        float ex = __expf(val - m);
        float ssum = ex;
        #pragma unroll
        for (int o = 16; o > 0; o >>= 1)
            ssum += __shfl_xor_sync(0xffffffffu, ssum, o);
        float lse = m + logf(ssum);
        int i0 = n * CC + t;
        if (i0 < out_size) out[i0] = val;                 // h2
        int i1 = NN * CC + i0;
        if (i1 < out_size) out[i1] = val - lse;           // log_softmax(h2)
    }
}

// ---------------- launch -----------------------------------------------------
extern "C" void kernel_launch(void* const* d_in, const int* in_sizes, int n_in,
                              void* d_out, int out_size) {
    const float* x     = (const float*)d_in[0];
    const int*   ei32  = (const int*)d_in[1];   // int32 or int64 (probed)
    const float* ea    = (const float*)d_in[2];
    const float* W1    = (const float*)d_in[3];
    const float* attS1 = (const float*)d_in[4];
    const float* attD1 = (const float*)d_in[5];
    const float* We1   = (const float*)d_in[6];
    const float* attE1 = (const float*)d_in[7];
    const float* b1    = (const float*)d_in[8];
    const float* W2    = (const float*)d_in[9];
    const float* attS2 = (const float*)d_in[10];
    const float* attD2 = (const float*)d_in[11];
    const float* b2    = (const float*)d_in[12];
    float* out = (float*)d_out;

    static int smem_set = 0;
    if (!smem_set) {
        cudaFuncSetAttribute(gemm_kernel,
                             cudaFuncAttributeMaxDynamicSharedMemorySize, GEMM_SMEM);
        smem_set = 1;
    }

    // --- edge-index dtype probe + conversion ---
    detect_kernel<<<1, 32>>>(ei32);
    convert_kernel<<<(EE + 255) / 256, 256>>>(ei32);

    // --- input conversions (independent of edges) ---
    convx_kernel<<<(NN * FIN + 255) / 256, 256>>>(x);
    wt_kernel<<<(FIN * HC + 255) / 256, 256>>>(0, W1);
    wt_kernel<<<(HC * HC + 255) / 256, 256>>>(1, W2);

    // --- CSR by destination ---
    zero_deg_kernel<<<(NN + 255) / 256, 256>>>();
    deg_kernel<<<(ET + 255) / 256, 256>>>();
    scan_kernel<<<1, 1024>>>();
    scatter_kernel<<<(ET + 255) / 256, 256>>>();
    loop_mean_kernel<<<(NN + 7) / 8, 256>>>(ea);

    // --- edge attention scalars (folded W_e1 @ att_edge1) ---
    ve_kernel<<<1, HC>>>(We1, attE1);
    ae_kernel<<<(ET * HH + 255) / 256, 256>>>(ea);

    // --- layer 1 ---
    gemm_kernel<<<dim3(HC / BN, NPAD / BM), 256, GEMM_SMEM>>>(0);
    dots_kernel<<<NN, HC>>>(0, attS1, attD1);
    agg1_kernel<<<NN, HC>>>(b1);

    // --- layer 2 ---
    gemm_kernel<<<dim3(HC / BN, NPAD / BM), 256, GEMM_SMEM>>>(1);
    dots_kernel<<<NN, HC>>>(1, attS2, attD2);
    agg2_kernel<<<NN, HC>>>(b2, out, out_size);
}

// round 9
// speedup vs baseline: 1.4547x; 1.2304x over previous
#include <cuda_runtime.h>
#include <cuda_bf16.h>
#include <math.h>
#include <stdint.h>

// Problem constants (shapes fixed by dataset).
#define NN    25000
#define NPAD  25088          // 196*128, padded row count for MMA tiles
#define EE    400000
#define ET    (EE + NN)
#define FIN   256
#define CC    32
#define HH    12
#define HC    384
#define NEG_SLOPE 0.2f
#define CHUNK 64

// ---------------- scratch (static device globals; allocation-free) ----------
__device__ __align__(16) __nv_bfloat16 d_xb[(size_t)NPAD * FIN];   // zero-padded tail
__device__ __align__(16) __nv_bfloat16 d_xs[(size_t)NPAD * FIN];
__device__ __align__(16) __nv_bfloat16 d_h1b[(size_t)NPAD * HC];
__device__ __align__(16) __nv_bfloat16 d_h1s[(size_t)NPAD * HC];
__device__ __align__(16) __nv_bfloat16 d_w1b[(size_t)HC * FIN];
__device__ __align__(16) __nv_bfloat16 d_w1s[(size_t)HC * FIN];
__device__ __align__(16) __nv_bfloat16 d_w2b[(size_t)HC * HC];
__device__ __align__(16) __nv_bfloat16 d_w2s[(size_t)HC * HC];
__device__ __align__(16) float d_hx1[(size_t)NN * HC];
__device__ __align__(16) float d_hx2[(size_t)NN * HC];
__device__ float d_as1[NN * HH], d_ad1[NN * HH];
__device__ float d_as2[NN * HH], d_ad2[NN * HH];
__device__ float d_loop_attr[(size_t)NN * CC];
__device__ float d_Ve[CC * HH];
__device__ float d_ae[(size_t)ET * HH];
__device__ int   d_deg[NN];
__device__ int   d_rowptr[NN + 1];
__device__ int   d_cursor[NN];
__device__ int   d_csr_src[ET];
__device__ int   d_csr_eid[ET];
__device__ int   d_esrc[EE];
__device__ int   d_edst[EE];
__device__ int   d_is64;

// ---------------- edge-index dtype probe + conversion ------------------------
__global__ void detect_kernel(const int* __restrict__ ei32) {
    if (threadIdx.x == 0) {
        int z = 1;
        #pragma unroll
        for (int i = 1; i < 64; i += 2) z &= (ei32[i] == 0);
        d_is64 = z;
    }
}
__global__ void convert_kernel(const int* __restrict__ ei32) {
    int e = blockIdx.x * blockDim.x + threadIdx.x;
    if (e >= EE) return;
    if (d_is64) {
        d_esrc[e] = ei32[2 * (size_t)e];
        d_edst[e] = ei32[2 * ((size_t)EE + e)];
    } else {
        d_esrc[e] = ei32[e];
        d_edst[e] = ei32[EE + e];
    }
}

// ---------------- preprocessing ----------------------------------------------
__global__ void zero_deg_kernel() {
    int i = blockIdx.x * blockDim.x + threadIdx.x;
    if (i < NN) d_deg[i] = 0;
}
__global__ void deg_kernel() {
    int idx = blockIdx.x * blockDim.x + threadIdx.x;
    if (idx >= ET) return;
    int dst = (idx < EE) ? d_edst[idx] : (idx - EE);
    atomicAdd(&d_deg[dst], 1);
}
__global__ void scan_kernel() {
    __shared__ int warpsum[32];
    __shared__ int s_carry;
    int t = threadIdx.x;
    if (t == 0) s_carry = 0;
    __syncthreads();
    for (int base = 0; base < NN; base += 1024) {
        int i = base + t;
        int v = (i < NN) ? d_deg[i] : 0;
        int lane = t & 31, w = t >> 5;
        int x = v;
        #pragma unroll
        for (int o = 1; o < 32; o <<= 1) {
            int y = __shfl_up_sync(0xffffffffu, x, o);
            if (lane >= o) x += y;
        }
        if (lane == 31) warpsum[w] = x;
        __syncthreads();
        if (w == 0) {
            int s = warpsum[lane];
            #pragma unroll
            for (int o = 1; o < 32; o <<= 1) {
                int y = __shfl_up_sync(0xffffffffu, s, o);
                if (lane >= o) s += y;
            }
            warpsum[lane] = s;
        }
        __syncthreads();
        int incl = x + (w > 0 ? warpsum[w - 1] : 0);
        int excl = incl - v;
        int carry = s_carry;
        if (i < NN) { d_rowptr[i] = carry + excl; d_cursor[i] = carry + excl; }
        __syncthreads();
        if (t == 1023) s_carry = carry + incl;
        __syncthreads();
    }
    if (t == 0) d_rowptr[NN] = s_carry;
}
__global__ void scatter_kernel() {
    int idx = blockIdx.x * blockDim.x + threadIdx.x;
    if (idx >= ET) return;
    int src, dst;
    if (idx < EE) { src = d_esrc[idx]; dst = d_edst[idx]; }
    else          { src = dst = idx - EE; }
    int p = atomicAdd(&d_cursor[dst], 1);
    d_csr_src[p] = src;
    d_csr_eid[p] = idx;
}

// PyG add_self_loops fill_value='mean': per-dst mean of incoming edge_attr
__global__ void loop_mean_kernel(const float* __restrict__ ea) {
    int n = blockIdx.x * 8 + (threadIdx.x >> 5);
    if (n >= NN) return;
    int lane = threadIdx.x & 31;
    int beg = d_rowptr[n], end = d_rowptr[n + 1];
    float s = 0.f;
    for (int p = beg; p < end; p++) {
        int eid = d_csr_eid[p];
        if (eid < EE) s += ea[(size_t)eid * CC + lane];
    }
    float cnt = (float)(end - beg - 1);   // self-loop excluded
    d_loop_attr[n * CC + lane] = s / fmaxf(cnt, 1.f);
}

// V_e[k,h] = sum_c W_e1[k, h*32+c] * att_e[h,c]
__global__ void ve_kernel(const float* __restrict__ We,
                          const float* __restrict__ atte) {
    int t = threadIdx.x;          // 384 = 32k x 12h
    int k = t / HH, h = t - HH * (t / HH);
    float s = 0.f;
    #pragma unroll
    for (int c = 0; c < CC; c++)
        s = fmaf(We[k * HC + h * CC + c], atte[h * CC + c], s);
    d_Ve[k * HH + h] = s;
}

// a_e[e,h] = edge_attr_full[e,:] @ V_e[:,h]
// Block handles 32 edges: coalesced smem stage (rows read ONCE), then
// 384 threads = 32 edges x 12 heads, one 32-FMA smem dot each.
// EE % 32 == 0 -> no block straddles the real-edge / self-loop boundary.
__global__ void __launch_bounds__(384) ae_kernel(const float* __restrict__ ea) {
    __shared__ float s_row[32 * 33];   // pad 33 -> conflict-light
    __shared__ float sVe[CC * HH];
    int t = threadIdx.x;
    for (int i = t; i < CC * HH; i += 384) sVe[i] = d_Ve[i];
    int e0 = blockIdx.x * 32;
    int nrows = min(32, ET - e0);
    const float* gsrc = (e0 < EE) ? (ea + (size_t)e0 * CC)
                                  : (d_loop_attr + (size_t)(e0 - EE) * CC);
    for (int i = t; i < nrows * CC; i += 384) {
        int r = i >> 5, c = i & 31;
        s_row[r * 33 + c] = gsrc[i];
    }
    __syncthreads();
    if (t < nrows * HH) {
        int el = t / HH, hh = t - HH * el;
        float s = 0.f;
        #pragma unroll
        for (int k = 0; k < CC; k++)
            s = fmaf(s_row[el * 33 + k], sVe[k * HH + hh], s);
        d_ae[(size_t)(e0 + el) * HH + hh] = s;
    }
}

// ---------------- fp32 -> bf16 big/small split conversions --------------------
__global__ void convx_kernel(const float* __restrict__ x) {
    int idx = blockIdx.x * blockDim.x + threadIdx.x;
    if (idx >= NN * FIN) return;
    float v = x[idx];
    __nv_bfloat16 b = __float2bfloat16(v);
    d_xb[idx] = b;
    d_xs[idx] = __float2bfloat16(v - __bfloat162float(b));
}
// W [K, HC] -> W^T pairs [HC][K]
__global__ void wt_kernel(int which, const float* __restrict__ W) {
    int K = which ? HC : FIN;
    __nv_bfloat16* wb = which ? d_w2b : d_w1b;
    __nv_bfloat16* ws = which ? d_w2s : d_w1s;
    int idx = blockIdx.x * blockDim.x + threadIdx.x;
    if (idx >= K * HC) return;
    int k = idx / HC, n = idx - HC * (idx / HC);
    float v = W[idx];
    __nv_bfloat16 b = __float2bfloat16(v);
    wb[(size_t)n * K + k] = b;
    ws[(size_t)n * K + k] = __float2bfloat16(v - __bfloat162float(b));
}

// ---------------- bf16 mma.sync GEMM (3x split) + fused attention dots -------
#define BM 128
#define BN 128
#define BKK 64
#define ASTR 72
#define TILE_B (128 * ASTR * 2)
#define GEMM_SMEM (4 * TILE_B)   // 73728 bytes

__device__ __forceinline__ void mma16816(float* c, const uint32_t* a,
                                         const uint32_t* b) {
    asm volatile(
        "mma.sync.aligned.m16n8k16.row.col.f32.bf16.bf16.f32 "
        "{%0,%1,%2,%3}, {%4,%5,%6,%7}, {%8,%9}, {%0,%1,%2,%3};\n"
        : "+f"(c[0]), "+f"(c[1]), "+f"(c[2]), "+f"(c[3])
        : "r"(a[0]), "r"(a[1]), "r"(a[2]), "r"(a[3]), "r"(b[0]), "r"(b[1]));
}

__global__ void __launch_bounds__(256) gemm_kernel(
    int which, const float* __restrict__ attS, const float* __restrict__ attD) {
    extern __shared__ char smem[];
    __nv_bfloat16* sAb = (__nv_bfloat16*)(smem);
    __nv_bfloat16* sAs = (__nv_bfloat16*)(smem + TILE_B);
    __nv_bfloat16* sBb = (__nv_bfloat16*)(smem + 2 * TILE_B);
    __nv_bfloat16* sBs = (__nv_bfloat16*)(smem + 3 * TILE_B);

    const int Kt = which ? HC : FIN;
    const __nv_bfloat16* Ab  = which ? d_h1b : d_xb;
    const __nv_bfloat16* As_ = which ? d_h1s : d_xs;
    const __nv_bfloat16* Bb  = which ? d_w2b : d_w1b;
    const __nv_bfloat16* Bs  = which ? d_w2s : d_w1s;
    float* Cm   = which ? d_hx2 : d_hx1;
    float* as_o = which ? d_as2 : d_as1;
    float* ad_o = which ? d_ad2 : d_ad1;

    int tid = threadIdx.x;
    int wid = tid >> 5, lane = tid & 31;
    int wm = (wid & 3) * 32;     // warp m offset
    int wn = (wid >> 2) * 64;    // warp n offset
    int tq = lane >> 2, tr = lane & 3;

    int bm = blockIdx.y * BM;
    int bn = blockIdx.x * BN;

    float acc[2][8][4];
    #pragma unroll
    for (int mt = 0; mt < 2; mt++)
        #pragma unroll
        for (int nt = 0; nt < 8; nt++)
            #pragma unroll
            for (int q = 0; q < 4; q++) acc[mt][nt][q] = 0.f;

    int lrow = tid >> 1;
    int lcol = (tid & 1) * 32;

    for (int k0 = 0; k0 < Kt; k0 += BKK) {
        const uint4* gab = (const uint4*)(Ab  + (size_t)(bm + lrow) * Kt + k0 + lcol);
        const uint4* gas = (const uint4*)(As_ + (size_t)(bm + lrow) * Kt + k0 + lcol);
        const uint4* gbb = (const uint4*)(Bb  + (size_t)(bn + lrow) * Kt + k0 + lcol);
        const uint4* gbs = (const uint4*)(Bs  + (size_t)(bn + lrow) * Kt + k0 + lcol);
        uint4* pab = (uint4*)&sAb[lrow * ASTR + lcol];
        uint4* pas = (uint4*)&sAs[lrow * ASTR + lcol];
        uint4* pbb = (uint4*)&sBb[lrow * ASTR + lcol];
        uint4* pbs = (uint4*)&sBs[lrow * ASTR + lcol];
        #pragma unroll
        for (int i = 0; i < 4; i++) {
            pab[i] = gab[i];
            pas[i] = gas[i];
            pbb[i] = gbb[i];
            pbs[i] = gbs[i];
        }
        __syncthreads();
        #pragma unroll
        for (int s = 0; s < BKK / 16; s++) {
            int kk = s * 16 + tr * 2;
            uint32_t afb[2][4], afs[2][4];
            #pragma unroll
            for (int mt = 0; mt < 2; mt++) {
                int r0 = wm + mt * 16 + tq;
                afb[mt][0] = *(const uint32_t*)&sAb[r0 * ASTR + kk];
                afb[mt][1] = *(const uint32_t*)&sAb[(r0 + 8) * ASTR + kk];
                afb[mt][2] = *(const uint32_t*)&sAb[r0 * ASTR + kk + 8];
                afb[mt][3] = *(const uint32_t*)&sAb[(r0 + 8) * ASTR + kk + 8];
                afs[mt][0] = *(const uint32_t*)&sAs[r0 * ASTR + kk];
                afs[mt][1] = *(const uint32_t*)&sAs[(r0 + 8) * ASTR + kk];
                afs[mt][2] = *(const uint32_t*)&sAs[r0 * ASTR + kk + 8];
                afs[mt][3] = *(const uint32_t*)&sAs[(r0 + 8) * ASTR + kk + 8];
            }
            #pragma unroll
            for (int nt = 0; nt < 8; nt++) {
                int nr = wn + nt * 8 + tq;
                uint32_t bfb[2], bfs[2];
                bfb[0] = *(const uint32_t*)&sBb[nr * ASTR + kk];
                bfb[1] = *(const uint32_t*)&sBb[nr * ASTR + kk + 8];
                bfs[0] = *(const uint32_t*)&sBs[nr * ASTR + kk];
                bfs[1] = *(const uint32_t*)&sBs[nr * ASTR + kk + 8];
                #pragma unroll
                for (int mt = 0; mt < 2; mt++) {
                    mma16816(acc[mt][nt], afb[mt], bfb);
                    mma16816(acc[mt][nt], afb[mt], bfs);
                    mma16816(acc[mt][nt], afs[mt], bfb);
                }
            }
        }
        __syncthreads();
    }
    // ---- epilogue: store C + fused per-head attention dots ----
    float sD[2][2][2], dD[2][2][2];   // [mt][rowhalf][head-local]
    #pragma unroll
    for (int mt = 0; mt < 2; mt++)
        #pragma unroll
        for (int hf = 0; hf < 2; hf++)
            #pragma unroll
            for (int hd = 0; hd < 2; hd++) { sD[mt][hf][hd] = 0.f; dD[mt][hf][hd] = 0.f; }

    #pragma unroll
    for (int mt = 0; mt < 2; mt++) {
        int r0 = bm + wm + mt * 16 + tq;
        #pragma unroll
        for (int nt = 0; nt < 8; nt++) {
            int c0 = bn + wn + nt * 8 + tr * 2;
            int hd = nt >> 2;
            float aS0 = attS[c0], aS1 = attS[c0 + 1];
            float aD0 = attD[c0], aD1 = attD[c0 + 1];
            sD[mt][0][hd] += acc[mt][nt][0] * aS0 + acc[mt][nt][1] * aS1;
            sD[mt][1][hd] += acc[mt][nt][2] * aS0 + acc[mt][nt][3] * aS1;
            dD[mt][0][hd] += acc[mt][nt][0] * aD0 + acc[mt][nt][1] * aD1;
            dD[mt][1][hd] += acc[mt][nt][2] * aD0 + acc[mt][nt][3] * aD1;
            if (r0 < NN)
                *(float2*)&Cm[(size_t)r0 * HC + c0] =
                    make_float2(acc[mt][nt][0], acc[mt][nt][1]);
            if (r0 + 8 < NN)
                *(float2*)&Cm[(size_t)(r0 + 8) * HC + c0] =
                    make_float2(acc[mt][nt][2], acc[mt][nt][3]);
        }
    }
    // reduce the dots across the 4 tr lanes (lane = tq*4+tr)
    #pragma unroll
    for (int mt = 0; mt < 2; mt++)
        #pragma unroll
        for (int hf = 0; hf < 2; hf++)
            #pragma unroll
            for (int hd = 0; hd < 2; hd++) {
                float s = sD[mt][hf][hd], d = dD[mt][hf][hd];
                s += __shfl_xor_sync(0xffffffffu, s, 1);
                s += __shfl_xor_sync(0xffffffffu, s, 2);
                d += __shfl_xor_sync(0xffffffffu, d, 1);
                d += __shfl_xor_sync(0xffffffffu, d, 2);
                sD[mt][hf][hd] = s; dD[mt][hf][hd] = d;
            }
    if (tr == 0) {
        int hbase = (bn + wn) >> 5;
        #pragma unroll
        for (int mt = 0; mt < 2; mt++)
            #pragma unroll
            for (int hf = 0; hf < 2; hf++) {
                int row = bm + wm + mt * 16 + tq + hf * 8;
                if (row < NN) {
                    #pragma unroll
                    for (int hd = 0; hd < 2; hd++) {
                        as_o[row * HH + hbase + hd] = sD[mt][hf][hd];
                        ad_o[row * HH + hbase + hd] = dD[mt][hf][hd];
                    }
                }
            }
    }
}

// ---------------- layer-1 aggregation: single pass, deferred normalization ---
// out = (sum_j exp(e_j) * hx[src_j]) / (sum_j exp(e_j));  |e| <= ~2 -> no max
__global__ void __launch_bounds__(HC) agg1_kernel(const float* __restrict__ b1) {
    int n = blockIdx.x;
    int t = threadIdx.x;
    int h = t >> 5;
    __shared__ float s_ad[HH], s_den[HH];
    __shared__ int   s_src[CHUNK];
    __shared__ float s_alpha[CHUNK * HH];

    int beg = d_rowptr[n], deg = d_rowptr[n + 1] - beg;
    if (t < HH) { s_ad[t] = d_ad1[n * HH + t]; s_den[t] = 0.f; }
    __syncthreads();

    float acc = 0.f;
    float den_loc = 0.f;          // this thread's head = t % HH (384 % 12 == 0)
    for (int base = 0; base < deg; base += CHUNK) {
        int cn = min(CHUNK, deg - base);
        for (int idx = t; idx < cn * HH; idx += HC) {
            int j = idx / HH, hh = idx - HH * j;
            int p = beg + base + j;
            int src = d_csr_src[p], eid = d_csr_eid[p];
            float e = d_as1[src * HH + hh] + s_ad[hh] + d_ae[(size_t)eid * HH + hh];
            e = (e > 0.f) ? e : NEG_SLOPE * e;
            float ex = __expf(e);
            s_alpha[j * HH + hh] = ex;
            den_loc += ex;
            if (hh == 0) s_src[j] = src;
        }
        __syncthreads();
        #pragma unroll 4
        for (int j = 0; j < cn; j++)
            acc = fmaf(s_alpha[j * HH + h], d_hx1[(size_t)s_src[j] * HC + t], acc);
        __syncthreads();
    }
    atomicAdd(&s_den[t % HH], den_loc);
    __syncthreads();

    float v = acc / s_den[h] + b1[t];
    v = (v > 0.f) ? v : expm1f(v);                 // ELU
    __nv_bfloat16 big = __float2bfloat16(v);
    d_h1b[(size_t)n * HC + t] = big;
    d_h1s[(size_t)n * HC + t] = __float2bfloat16(v - __bfloat162float(big));
}

// ---------------- layer-2 aggregation (mean over heads + log_softmax) --------
__global__ void __launch_bounds__(HC) agg2_kernel(const float* __restrict__ b2,
                                                  float* __restrict__ out,
                                                  int out_size) {
    int n = blockIdx.x;
    int t = threadIdx.x;
    int h = t >> 5;
    __shared__ float s_ad[HH], s_den[HH];
    __shared__ int   s_src[CHUNK];
    __shared__ float s_alpha[CHUNK * HH];
    __shared__ float s_out[HC];

    int beg = d_rowptr[n], deg = d_rowptr[n + 1] - beg;
    if (t < HH) { s_ad[t] = d_ad2[n * HH + t]; s_den[t] = 0.f; }
    __syncthreads();

    float acc = 0.f;
    float den_loc = 0.f;
    for (int base = 0; base < deg; base += CHUNK) {
        int cn = min(CHUNK, deg - base);
        for (int idx = t; idx < cn * HH; idx += HC) {
            int j = idx / HH, hh = idx - HH * j;
            int src = d_csr_src[beg + base + j];
            float e = d_as2[src * HH + hh] + s_ad[hh];
            e = (e > 0.f) ? e : NEG_SLOPE * e;
            float ex = __expf(e);
            s_alpha[j * HH + hh] = ex;
            den_loc += ex;
            if (hh == 0) s_src[j] = src;
        }
        __syncthreads();
        #pragma unroll 4
        for (int j = 0; j < cn; j++)
            acc = fmaf(s_alpha[j * HH + h], d_hx2[(size_t)s_src[j] * HC + t], acc);
        __syncthreads();
    }
    atomicAdd(&s_den[t % HH], den_loc);
    __syncthreads();

    s_out[t] = acc / s_den[h];
    __syncthreads();
    if (t < CC) {
        float s = 0.f;
        #pragma unroll
        for (int hh = 0; hh < HH; hh++) s += s_out[hh * CC + t];
        float val = s * (1.f / (float)HH) + b2[t];
        float m = val;
        #pragma unroll
        for (int o = 16; o > 0; o >>= 1)
            m = fmaxf(m, __shfl_xor_sync(0xffffffffu, m, o));
        float ex = __expf(val - m);
        float ssum = ex;
        #pragma unroll
        for (int o = 16; o > 0; o >>= 1)
            ssum += __shfl_xor_sync(0xffffffffu, ssum, o);
        float lse = m + logf(ssum);
        int i0 = n * CC + t;
        if (i0 < out_size) out[i0] = val;                 // h2
        int i1 = NN * CC + i0;
        if (i1 < out_size) out[i1] = val - lse;           // log_softmax(h2)
    }
}

// ---------------- launch -----------------------------------------------------
extern "C" void kernel_launch(void* const* d_in, const int* in_sizes, int n_in,
                              void* d_out, int out_size) {
    const float* x     = (const float*)d_in[0];
    const int*   ei32  = (const int*)d_in[1];
    const float* ea    = (const float*)d_in[2];
    const float* W1    = (const float*)d_in[3];
    const float* attS1 = (const float*)d_in[4];
    const float* attD1 = (const float*)d_in[5];
    const float* We1   = (const float*)d_in[6];
    const float* attE1 = (const float*)d_in[7];
    const float* b1    = (const float*)d_in[8];
    const float* W2    = (const float*)d_in[9];
    const float* attS2 = (const float*)d_in[10];
    const float* attD2 = (const float*)d_in[11];
    const float* b2    = (const float*)d_in[12];
    float* out = (float*)d_out;

    static int smem_set = 0;
    if (!smem_set) {
        cudaFuncSetAttribute(gemm_kernel,
                             cudaFuncAttributeMaxDynamicSharedMemorySize, GEMM_SMEM);
        smem_set = 1;
    }

    // --- edge-index dtype probe + conversion ---
    detect_kernel<<<1, 32>>>(ei32);
    convert_kernel<<<(EE + 255) / 256, 256>>>(ei32);

    // --- input conversions ---
    convx_kernel<<<(NN * FIN + 255) / 256, 256>>>(x);
    wt_kernel<<<(FIN * HC + 255) / 256, 256>>>(0, W1);
    wt_kernel<<<(HC * HC + 255) / 256, 256>>>(1, W2);

    // --- CSR by destination ---
    zero_deg_kernel<<<(NN + 255) / 256, 256>>>();
    deg_kernel<<<(ET + 255) / 256, 256>>>();
    scan_kernel<<<1, 1024>>>();
    scatter_kernel<<<(ET + 255) / 256, 256>>>();
    loop_mean_kernel<<<(NN + 7) / 8, 256>>>(ea);

    // --- edge attention scalars ---
    ve_kernel<<<1, HC>>>(We1, attE1);
    ae_kernel<<<(ET + 31) / 32, 384>>>(ea);

    // --- layer 1 ---
    gemm_kernel<<<dim3(HC / BN, NPAD / BM), 256, GEMM_SMEM>>>(0, attS1, attD1);
    agg1_kernel<<<NN, HC>>>(b1);

    // --- layer 2 ---
    gemm_kernel<<<dim3(HC / BN, NPAD / BM), 256, GEMM_SMEM>>>(1, attS2, attD2);
    agg2_kernel<<<NN, HC>>>(b2, out, out_size);
}

// round 12
// speedup vs baseline: 1.4999x; 1.0310x over previous
#include <cuda_runtime.h>
#include <cuda_bf16.h>
#include <math.h>
#include <stdint.h>

// Problem constants (shapes fixed by dataset).
#define NN    25000
#define NPAD  25088          // 196*128, padded row count for MMA tiles
#define EE    400000
#define ET    (EE + NN)
#define FIN   256
#define CC    32
#define HH    12
#define HC    384
#define NEG_SLOPE 0.2f
#define CHUNK 64

// ---------------- scratch (static device globals; allocation-free) ----------
// Tail rows [NN, NPAD) stay zero (zero-initialized, never written) -> safe MMA pads.
__device__ __align__(16) __nv_bfloat16 d_xb[(size_t)NPAD * FIN];
__device__ __align__(16) __nv_bfloat16 d_xs[(size_t)NPAD * FIN];
__device__ __align__(16) __nv_bfloat16 d_h1b[(size_t)NPAD * HC];
__device__ __align__(16) __nv_bfloat16 d_h1s[(size_t)NPAD * HC];
__device__ __align__(16) __nv_bfloat16 d_w1b[(size_t)HC * FIN];
__device__ __align__(16) __nv_bfloat16 d_w1s[(size_t)HC * FIN];
__device__ __align__(16) __nv_bfloat16 d_w2b[(size_t)HC * HC];
__device__ __align__(16) __nv_bfloat16 d_w2s[(size_t)HC * HC];
__device__ __align__(16) float d_hx1[(size_t)NN * HC];
__device__ __align__(16) float d_hx2[(size_t)NN * HC];
__device__ float d_as1[NN * HH], d_ad1[NN * HH];
__device__ float d_as2[NN * HH], d_ad2[NN * HH];
__device__ float d_loop_attr[(size_t)NN * CC];
__device__ float d_Ve[CC * HH];
__device__ float d_ae[(size_t)ET * HH];
__device__ int   d_deg[NN];
__device__ int   d_rowptr[NN + 1];
__device__ int   d_cursor[NN];
__device__ int   d_csr_src[ET];
__device__ int   d_csr_eid[ET];
__device__ int   d_esrc[EE];
__device__ int   d_edst[EE];

// ---------------- zero pass (d_deg must be re-zeroed every call) -------------
__global__ void zero_deg_kernel() {
    int i = blockIdx.x * blockDim.x + threadIdx.x;
    if (i < NN) d_deg[i] = 0;
}

// ---------------- convert: dtype probe + edge split + degree + Ve ------------
// JAX with x64 disabled silently downgrades int64 -> int32. For int64 (< 2^31)
// every odd int32 slot is a zero high word; for int32 they're random node ids.
// Last block computes V_e[k,h] = sum_c W_e1[k, h*32+c] * att_e[h,c].
__global__ void __launch_bounds__(256) convert_kernel(
    const int* __restrict__ ei32, const float* __restrict__ We,
    const float* __restrict__ atte) {
    if (blockIdx.x == gridDim.x - 1) {           // Ve block
        for (int t = threadIdx.x; t < CC * HH; t += 256) {
            int k = t / HH, h = t - HH * (t / HH);
            float s = 0.f;
            #pragma unroll
            for (int c = 0; c < CC; c++)
                s = fmaf(We[k * HC + h * CC + c], atte[h * CC + c], s);
            d_Ve[k * HH + h] = s;
        }
        return;
    }
    __shared__ int s64;
    if (threadIdx.x == 0) {
        int z = 1;
        #pragma unroll
        for (int i = 1; i < 64; i += 2) z &= (ei32[i] == 0);
        s64 = z;
    }
    __syncthreads();
    int e = blockIdx.x * 256 + threadIdx.x;
    if (e < EE) {
        int src, dst;
        if (s64) {
            src = ei32[2 * (size_t)e];
            dst = ei32[2 * ((size_t)EE + e)];
        } else {
            src = ei32[e];
            dst = ei32[EE + e];
        }
        d_esrc[e] = src;
        d_edst[e] = dst;
        atomicAdd(&d_deg[dst], 1);
    }
}

// single-block exclusive scan over (deg + 1 self-loop) -> rowptr & cursor
__global__ void scan_kernel() {
    __shared__ int warpsum[32];
    __shared__ int s_carry;
    int t = threadIdx.x;
    if (t == 0) s_carry = 0;
    __syncthreads();
    for (int base = 0; base < NN; base += 1024) {
        int i = base + t;
        int v = (i < NN) ? (d_deg[i] + 1) : 0;   // +1: self loop
        int lane = t & 31, w = t >> 5;
        int x = v;
        #pragma unroll
        for (int o = 1; o < 32; o <<= 1) {
            int y = __shfl_up_sync(0xffffffffu, x, o);
            if (lane >= o) x += y;
        }
        if (lane == 31) warpsum[w] = x;
        __syncthreads();
        if (w == 0) {
            int s = warpsum[lane];
            #pragma unroll
            for (int o = 1; o < 32; o <<= 1) {
                int y = __shfl_up_sync(0xffffffffu, s, o);
                if (lane >= o) s += y;
            }
            warpsum[lane] = s;
        }
        __syncthreads();
        int incl = x + (w > 0 ? warpsum[w - 1] : 0);
        int excl = incl - v;
        int carry = s_carry;
        if (i < NN) { d_rowptr[i] = carry + excl; d_cursor[i] = carry + excl; }
        __syncthreads();
        if (t == 1023) s_carry = carry + incl;
        __syncthreads();
    }
    if (t == 0) d_rowptr[NN] = s_carry;
}

__global__ void scatter_kernel() {
    int idx = blockIdx.x * blockDim.x + threadIdx.x;
    if (idx >= ET) return;
    int src, dst;
    if (idx < EE) { src = d_esrc[idx]; dst = d_edst[idx]; }
    else          { src = dst = idx - EE; }
    int p = atomicAdd(&d_cursor[dst], 1);
    d_csr_src[p] = src;
    d_csr_eid[p] = idx;
}

// PyG add_self_loops fill_value='mean': per-dst mean of incoming edge_attr
__global__ void loop_mean_kernel(const float* __restrict__ ea) {
    int n = blockIdx.x * 8 + (threadIdx.x >> 5);
    if (n >= NN) return;
    int lane = threadIdx.x & 31;
    int beg = d_rowptr[n], end = d_rowptr[n + 1];
    float s = 0.f;
    for (int p = beg; p < end; p++) {
        int eid = d_csr_eid[p];
        if (eid < EE) s += ea[(size_t)eid * CC + lane];
    }
    float cnt = (float)(end - beg - 1);   // self-loop excluded
    d_loop_attr[n * CC + lane] = s / fmaxf(cnt, 1.f);
}

// a_e[e,h] = edge_attr_full[e,:] @ V_e[:,h]   (rows staged once in smem)
__global__ void __launch_bounds__(384) ae_kernel(const float* __restrict__ ea) {
    __shared__ float s_row[32 * 33];
    __shared__ float sVe[CC * HH];
    int t = threadIdx.x;
    for (int i = t; i < CC * HH; i += 384) sVe[i] = d_Ve[i];
    int e0 = blockIdx.x * 32;
    int nrows = min(32, ET - e0);
    const float* gsrc = (e0 < EE) ? (ea + (size_t)e0 * CC)
                                  : (d_loop_attr + (size_t)(e0 - EE) * CC);
    for (int i = t; i < nrows * CC; i += 384) {
        int r = i >> 5, c = i & 31;
        s_row[r * 33 + c] = gsrc[i];
    }
    __syncthreads();
    if (t < nrows * HH) {
        int el = t / HH, hh = t - HH * el;
        float s = 0.f;
        #pragma unroll
        for (int k = 0; k < CC; k++)
            s = fmaf(s_row[el * 33 + k], sVe[k * HH + hh], s);
        d_ae[(size_t)(e0 + el) * HH + hh] = s;
    }
}

// ---------------- fp32 -> bf16 big/small split conversions --------------------
__global__ void convx_kernel(const float* __restrict__ x) {
    int idx = blockIdx.x * blockDim.x + threadIdx.x;
    if (idx >= NN * FIN) return;
    float v = x[idx];
    __nv_bfloat16 b = __float2bfloat16(v);
    d_xb[idx] = b;
    d_xs[idx] = __float2bfloat16(v - __bfloat162float(b));
}
// Both weights, one launch: W [K, HC] -> W^T pairs [HC][K]
#define W1ELTS (FIN * HC)
#define W2ELTS (HC * HC)
__global__ void wt_kernel(const float* __restrict__ W1,
                          const float* __restrict__ W2) {
    int idx = blockIdx.x * blockDim.x + threadIdx.x;
    if (idx < W1ELTS) {
        int k = idx / HC, n = idx - HC * (idx / HC);
        float v = W1[idx];
        __nv_bfloat16 b = __float2bfloat16(v);
        d_w1b[(size_t)n * FIN + k] = b;
        d_w1s[(size_t)n * FIN + k] = __float2bfloat16(v - __bfloat162float(b));
    } else if (idx < W1ELTS + W2ELTS) {
        int i2 = idx - W1ELTS;
        int k = i2 / HC, n = i2 - HC * (i2 / HC);
        float v = W2[i2];
        __nv_bfloat16 b = __float2bfloat16(v);
        d_w2b[(size_t)n * HC + k] = b;
        d_w2s[(size_t)n * HC + k] = __float2bfloat16(v - __bfloat162float(b));
    }
}

// ---------------- bf16 mma.sync GEMM (3x split) + fused dots, cp.async -------
#define BM 128
#define BN 128
#define BKK 64
#define ASTR 72                        // padded smem row stride (elements)
#define TILE_B (128 * ASTR * 2)        // 18432 bytes per array
#define GEMM_SMEM (8 * TILE_B)         // 2 stages x 4 arrays = 147456 bytes

__device__ __forceinline__ void cp16(uint32_t saddr, const void* g) {
    asm volatile("cp.async.ca.shared.global [%0], [%1], 16;"
                 :: "r"(saddr), "l"(g));
}
__device__ __forceinline__ void mma16816(float* c, const uint32_t* a,
                                         const uint32_t* b) {
    asm volatile(
        "mma.sync.aligned.m16n8k16.row.col.f32.bf16.bf16.f32 "
        "{%0,%1,%2,%3}, {%4,%5,%6,%7}, {%8,%9}, {%0,%1,%2,%3};\n"
        : "+f"(c[0]), "+f"(c[1]), "+f"(c[2]), "+f"(c[3])
        : "r"(a[0]), "r"(a[1]), "r"(a[2]), "r"(a[3]), "r"(b[0]), "r"(b[1]));
}

__global__ void __launch_bounds__(256) gemm_kernel(
    int which, const float* __restrict__ attS, const float* __restrict__ attD) {
    extern __shared__ char smem[];
    uint32_t sbase = (uint32_t)__cvta_generic_to_shared(smem);

    const int Kt = which ? HC : FIN;
    const __nv_bfloat16* Ab  = which ? d_h1b : d_xb;
    const __nv_bfloat16* As_ = which ? d_h1s : d_xs;
    const __nv_bfloat16* Bb  = which ? d_w2b : d_w1b;
    const __nv_bfloat16* Bs  = which ? d_w2s : d_w1s;
    float* Cm   = which ? d_hx2 : d_hx1;
    float* as_o = which ? d_as2 : d_as1;
    float* ad_o = which ? d_ad2 : d_ad1;

    int tid = threadIdx.x;
    int wid = tid >> 5, lane = tid & 31;
    int wm = (wid & 3) * 32;
    int wn = (wid >> 2) * 64;
    int tq = lane >> 2, tr = lane & 3;

    int bm = blockIdx.y * BM;
    int bn = blockIdx.x * BN;

    // loader geometry: thread covers 32 bf16 (64 B) of one row of each array
    int lrow = tid >> 1;
    int lcol = (tid & 1) * 32;
    const char* gAb = (const char*)(Ab  + (size_t)(bm + lrow) * Kt + lcol);
    const char* gAs = (const char*)(As_ + (size_t)(bm + lrow) * Kt + lcol);
    const char* gBb = (const char*)(Bb  + (size_t)(bn + lrow) * Kt + lcol);
    const char* gBs = (const char*)(Bs  + (size_t)(bn + lrow) * Kt + lcol);
    uint32_t srow = (uint32_t)(lrow * (ASTR * 2) + lcol * 2);

    auto issue = [&](int kt, int st) {
        int kb = kt * BKK * 2;          // byte offset along K
        uint32_t s0 = sbase + (uint32_t)st * (4 * TILE_B) + srow;
        #pragma unroll
        for (int i = 0; i < 4; i++) {
            cp16(s0 + 0 * TILE_B + i * 16, gAb + kb + i * 16);
            cp16(s0 + 1 * TILE_B + i * 16, gAs + kb + i * 16);
            cp16(s0 + 2 * TILE_B + i * 16, gBb + kb + i * 16);
            cp16(s0 + 3 * TILE_B + i * 16, gBs + kb + i * 16);
        }
        asm volatile("cp.async.commit_group;");
    };

    float acc[2][8][4];
    #pragma unroll
    for (int mt = 0; mt < 2; mt++)
        #pragma unroll
        for (int nt = 0; nt < 8; nt++)
            #pragma unroll
            for (int q = 0; q < 4; q++) acc[mt][nt][q] = 0.f;

    const int KT = Kt / BKK;
    issue(0, 0);

    for (int kt = 0; kt < KT; kt++) {
        int st = kt & 1;
        if (kt + 1 < KT) {
            issue(kt + 1, st ^ 1);
            asm volatile("cp.async.wait_group 1;");
        } else {
            asm volatile("cp.async.wait_group 0;");
        }
        __syncthreads();

        const __nv_bfloat16* cAb = (const __nv_bfloat16*)(smem + st * 4 * TILE_B);
        const __nv_bfloat16* cAs = (const __nv_bfloat16*)(smem + st * 4 * TILE_B + TILE_B);
        const __nv_bfloat16* cBb = (const __nv_bfloat16*)(smem + st * 4 * TILE_B + 2 * TILE_B);
        const __nv_bfloat16* cBs = (const __nv_bfloat16*)(smem + st * 4 * TILE_B + 3 * TILE_B);

        #pragma unroll
        for (int s = 0; s < BKK / 16; s++) {
            int kk = s * 16 + tr * 2;
            uint32_t afb[2][4], afs[2][4];
            #pragma unroll
            for (int mt = 0; mt < 2; mt++) {
                int r0 = wm + mt * 16 + tq;
                afb[mt][0] = *(const uint32_t*)&cAb[r0 * ASTR + kk];
                afb[mt][1] = *(const uint32_t*)&cAb[(r0 + 8) * ASTR + kk];
                afb[mt][2] = *(const uint32_t*)&cAb[r0 * ASTR + kk + 8];
                afb[mt][3] = *(const uint32_t*)&cAb[(r0 + 8) * ASTR + kk + 8];
                afs[mt][0] = *(const uint32_t*)&cAs[r0 * ASTR + kk];
                afs[mt][1] = *(const uint32_t*)&cAs[(r0 + 8) * ASTR + kk];
                afs[mt][2] = *(const uint32_t*)&cAs[r0 * ASTR + kk + 8];
                afs[mt][3] = *(const uint32_t*)&cAs[(r0 + 8) * ASTR + kk + 8];
            }
            #pragma unroll
            for (int nt = 0; nt < 8; nt++) {
                int nr = wn + nt * 8 + tq;
                uint32_t bfb[2], bfs[2];
                bfb[0] = *(const uint32_t*)&cBb[nr * ASTR + kk];
                bfb[1] = *(const uint32_t*)&cBb[nr * ASTR + kk + 8];
                bfs[0] = *(const uint32_t*)&cBs[nr * ASTR + kk];
                bfs[1] = *(const uint32_t*)&cBs[nr * ASTR + kk + 8];
                #pragma unroll
                for (int mt = 0; mt < 2; mt++) {
                    mma16816(acc[mt][nt], afb[mt], bfb);
                    mma16816(acc[mt][nt], afb[mt], bfs);
                    mma16816(acc[mt][nt], afs[mt], bfb);
                }
            }
        }
        __syncthreads();
    }

    // ---- epilogue: store C + fused per-head attention dots ----
    float sD[2][2][2], dD[2][2][2];
    #pragma unroll
    for (int mt = 0; mt < 2; mt++)
        #pragma unroll
        for (int hf = 0; hf < 2; hf++)
            #pragma unroll
            for (int hd = 0; hd < 2; hd++) { sD[mt][hf][hd] = 0.f; dD[mt][hf][hd] = 0.f; }

    #pragma unroll
    for (int mt = 0; mt < 2; mt++) {
        int r0 = bm + wm + mt * 16 + tq;
        #pragma unroll
        for (int nt = 0; nt < 8; nt++) {
            int c0 = bn + wn + nt * 8 + tr * 2;
            int hd = nt >> 2;
            float aS0 = attS[c0], aS1 = attS[c0 + 1];
            float aD0 = attD[c0], aD1 = attD[c0 + 1];
            sD[mt][0][hd] += acc[mt][nt][0] * aS0 + acc[mt][nt][1] * aS1;
            sD[mt][1][hd] += acc[mt][nt][2] * aS0 + acc[mt][nt][3] * aS1;
            dD[mt][0][hd] += acc[mt][nt][0] * aD0 + acc[mt][nt][1] * aD1;
            dD[mt][1][hd] += acc[mt][nt][2] * aD0 + acc[mt][nt][3] * aD1;
            if (r0 < NN)
                *(float2*)&Cm[(size_t)r0 * HC + c0] =
                    make_float2(acc[mt][nt][0], acc[mt][nt][1]);
            if (r0 + 8 < NN)
                *(float2*)&Cm[(size_t)(r0 + 8) * HC + c0] =
                    make_float2(acc[mt][nt][2], acc[mt][nt][3]);
        }
    }
    #pragma unroll
    for (int mt = 0; mt < 2; mt++)
        #pragma unroll
        for (int hf = 0; hf < 2; hf++)
            #pragma unroll
            for (int hd = 0; hd < 2; hd++) {
                float s = sD[mt][hf][hd], d = dD[mt][hf][hd];
                s += __shfl_xor_sync(0xffffffffu, s, 1);
                s += __shfl_xor_sync(0xffffffffu, s, 2);
                d += __shfl_xor_sync(0xffffffffu, d, 1);
                d += __shfl_xor_sync(0xffffffffu, d, 2);
                sD[mt][hf][hd] = s; dD[mt][hf][hd] = d;
            }
    if (tr == 0) {
        int hbase = (bn + wn) >> 5;
        #pragma unroll
        for (int mt = 0; mt < 2; mt++)
            #pragma unroll
            for (int hf = 0; hf < 2; hf++) {
                int row = bm + wm + mt * 16 + tq + hf * 8;
                if (row < NN) {
                    #pragma unroll
                    for (int hd = 0; hd < 2; hd++) {
                        as_o[row * HH + hbase + hd] = sD[mt][hf][hd];
                        ad_o[row * HH + hbase + hd] = dD[mt][hf][hd];
                    }
                }
            }
    }
}

// ---------------- layer-1 aggregation: single pass, deferred normalization ---
__global__ void __launch_bounds__(HC) agg1_kernel(const float* __restrict__ b1) {
    int n = blockIdx.x;
    int t = threadIdx.x;
    int h = t >> 5;
    __shared__ float s_ad[HH], s_den[HH];
    __shared__ int   s_src[CHUNK];
    __shared__ float s_alpha[CHUNK * HH];

    int beg = d_rowptr[n], deg = d_rowptr[n + 1] - beg;
    if (t < HH) { s_ad[t] = d_ad1[n * HH + t]; s_den[t] = 0.f; }
    __syncthreads();

    float acc = 0.f;
    float den_loc = 0.f;
    for (int base = 0; base < deg; base += CHUNK) {
        int cn = min(CHUNK, deg - base);
        for (int idx = t; idx < cn * HH; idx += HC) {
            int j = idx / HH, hh = idx - HH * j;
            int p = beg + base + j;
            int src = d_csr_src[p], eid = d_csr_eid[p];
            float e = d_as1[src * HH + hh] + s_ad[hh] + d_ae[(size_t)eid * HH + hh];
            e = (e > 0.f) ? e : NEG_SLOPE * e;
            float ex = __expf(e);
            s_alpha[j * HH + hh] = ex;
            den_loc += ex;
            if (hh == 0) s_src[j] = src;
        }
        __syncthreads();
        #pragma unroll 8
        for (int j = 0; j < cn; j++)
            acc = fmaf(s_alpha[j * HH + h], d_hx1[(size_t)s_src[j] * HC + t], acc);
        __syncthreads();
    }
    atomicAdd(&s_den[t % HH], den_loc);
    __syncthreads();

    float v = acc / s_den[h] + b1[t];
    v = (v > 0.f) ? v : expm1f(v);                 // ELU
    __nv_bfloat16 big = __float2bfloat16(v);
    d_h1b[(size_t)n * HC + t] = big;
    d_h1s[(size_t)n * HC + t] = __float2bfloat16(v - __bfloat162float(big));
}

// ---------------- layer-2 aggregation (mean over heads + log_softmax) --------
__global__ void __launch_bounds__(HC) agg2_kernel(const float* __restrict__ b2,
                                                  float* __restrict__ out,
                                                  int out_size) {
    int n = blockIdx.x;
    int t = threadIdx.x;
    int h = t >> 5;
    __shared__ float s_ad[HH], s_den[HH];
    __shared__ int   s_src[CHUNK];
    __shared__ float s_alpha[CHUNK * HH];
    __shared__ float s_out[HC];

    int beg = d_rowptr[n], deg = d_rowptr[n + 1] - beg;
    if (t < HH) { s_ad[t] = d_ad2[n * HH + t]; s_den[t] = 0.f; }
    __syncthreads();

    float acc = 0.f;
    float den_loc = 0.f;
    for (int base = 0; base < deg; base += CHUNK) {
        int cn = min(CHUNK, deg - base);
        for (int idx = t; idx < cn * HH; idx += HC) {
            int j = idx / HH, hh = idx - HH * j;
            int src = d_csr_src[beg + base + j];
            float e = d_as2[src * HH + hh] + s_ad[hh];
            e = (e > 0.f) ? e : NEG_SLOPE * e;
            float ex = __expf(e);
            s_alpha[j * HH + hh] = ex;
            den_loc += ex;
            if (hh == 0) s_src[j] = src;
        }
        __syncthreads();
        #pragma unroll 8
        for (int j = 0; j < cn; j++)
            acc = fmaf(s_alpha[j * HH + h], d_hx2[(size_t)s_src[j] * HC + t], acc);
        __syncthreads();
    }
    atomicAdd(&s_den[t % HH], den_loc);
    __syncthreads();

    s_out[t] = acc / s_den[h];
    __syncthreads();
    if (t < CC) {
        float s = 0.f;
        #pragma unroll
        for (int hh = 0; hh < HH; hh++) s += s_out[hh * CC + t];
        float val = s * (1.f / (float)HH) + b2[t];
        float m = val;
        #pragma unroll
        for (int o = 16; o > 0; o >>= 1)
            m = fmaxf(m, __shfl_xor_sync(0xffffffffu, m, o));
        float ex = __expf(val - m);
        float ssum = ex;
        #pragma unroll
        for (int o = 16; o > 0; o >>= 1)
            ssum += __shfl_xor_sync(0xffffffffu, ssum, o);
        float lse = m + logf(ssum);
        int i0 = n * CC + t;
        if (i0 < out_size) out[i0] = val;                 // h2
        int i1 = NN * CC + i0;
        if (i1 < out_size) out[i1] = val - lse;           // log_softmax(h2)
    }
}

// ---------------- launch -----------------------------------------------------
extern "C" void kernel_launch(void* const* d_in, const int* in_sizes, int n_in,
                              void* d_out, int out_size) {
    const float* x     = (const float*)d_in[0];
    const int*   ei32  = (const int*)d_in[1];
    const float* ea    = (const float*)d_in[2];
    const float* W1    = (const float*)d_in[3];
    const float* attS1 = (const float*)d_in[4];
    const float* attD1 = (const float*)d_in[5];
    const float* We1   = (const float*)d_in[6];
    const float* attE1 = (const float*)d_in[7];
    const float* b1    = (const float*)d_in[8];
    const float* W2    = (const float*)d_in[9];
    const float* attS2 = (const float*)d_in[10];
    const float* attD2 = (const float*)d_in[11];
    const float* b2    = (const float*)d_in[12];
    float* out = (float*)d_out;

    cudaFuncSetAttribute(gemm_kernel,
                         cudaFuncAttributeMaxDynamicSharedMemorySize, GEMM_SMEM);

    // slot 0: zero degrees
    zero_deg_kernel<<<(NN + 255) / 256, 256>>>();
    // slot 1: probe dtype + split edges + degree histogram + Ve (extra block)
    convert_kernel<<<(EE + 255) / 256 + 1, 256>>>(ei32, We1, attE1);
    // slot 2: x -> bf16 split
    convx_kernel<<<(NN * FIN + 255) / 256, 256>>>(x);
    // slot 3: both weights -> transposed bf16 splits
    wt_kernel<<<(W1ELTS + W2ELTS + 255) / 256, 256>>>(W1, W2);
    // slot 4 (ncu-captured): layer-1 GEMM + fused dots
    gemm_kernel<<<dim3(HC / BN, NPAD / BM), 256, GEMM_SMEM>>>(0, attS1, attD1);
    // edge pipeline (independent of GEMM until agg1)
    scan_kernel<<<1, 1024>>>();
    scatter_kernel<<<(ET + 255) / 256, 256>>>();
    loop_mean_kernel<<<(NN + 7) / 8, 256>>>(ea);
    ae_kernel<<<(ET + 31) / 32, 384>>>(ea);
    // layer 1 aggregation
    agg1_kernel<<<NN, HC>>>(b1);
    // layer 2
    gemm_kernel<<<dim3(HC / BN, NPAD / BM), 256, GEMM_SMEM>>>(1, attS2, attD2);
    agg2_kernel<<<NN, HC>>>(b2, out, out_size);
}

// round 14
// speedup vs baseline: 1.5568x; 1.0380x over previous
#include <cuda_runtime.h>
#include <cuda_bf16.h>
#include <math.h>
#include <stdint.h>

// Problem constants (shapes fixed by dataset).
#define NN    25000
#define NPAD  25088          // 196*128, padded row count for MMA tiles
#define EE    400000
#define ET    (EE + NN)
#define FIN   256
#define CC    32
#define HH    12
#define HC    384
#define NEG_SLOPE 0.2f
#define CHUNK 64

// ---------------- scratch (static device globals; allocation-free) ----------
__device__ __align__(16) __nv_bfloat16 d_xb[(size_t)NPAD * FIN];
__device__ __align__(16) __nv_bfloat16 d_xs[(size_t)NPAD * FIN];
__device__ __align__(16) __nv_bfloat16 d_h1b[(size_t)NPAD * HC];
__device__ __align__(16) __nv_bfloat16 d_h1s[(size_t)NPAD * HC];
__device__ __align__(16) __nv_bfloat16 d_w1b[(size_t)HC * FIN];
__device__ __align__(16) __nv_bfloat16 d_w1s[(size_t)HC * FIN];
__device__ __align__(16) __nv_bfloat16 d_w2b[(size_t)HC * HC];
__device__ __align__(16) __nv_bfloat16 d_w2s[(size_t)HC * HC];
__device__ __align__(16) float d_hx1[(size_t)NN * HC];
__device__ __align__(16) float d_hx2[(size_t)NN * HC];
__device__ float d_as1[NN * HH], d_ad1[NN * HH];
__device__ float d_as2[NN * HH], d_ad2[NN * HH];
__device__ float d_loop_attr[(size_t)NN * CC];
__device__ float d_Ve[CC * HH];
__device__ float d_ae[(size_t)ET * HH];
__device__ int   d_deg[NN];
__device__ int   d_rowptr[NN + 1];
__device__ int   d_cursor[NN];
__device__ int   d_csr_src[ET];
__device__ int   d_csr_eid[ET];
__device__ int   d_esrc[EE];
__device__ int   d_edst[EE];

// ---------------- zero pass --------------------------------------------------
__global__ void zero_deg_kernel() {
    int i = blockIdx.x * blockDim.x + threadIdx.x;
    if (i < NN) d_deg[i] = 0;
}

// ---------------- convert: dtype probe + edge split + degree + Ve ------------
__global__ void __launch_bounds__(256) convert_kernel(
    const int* __restrict__ ei32, const float* __restrict__ We,
    const float* __restrict__ atte) {
    if (blockIdx.x == gridDim.x - 1) {           // Ve block
        for (int t = threadIdx.x; t < CC * HH; t += 256) {
            int k = t / HH, h = t - HH * (t / HH);
            float s = 0.f;
            #pragma unroll
            for (int c = 0; c < CC; c++)
                s = fmaf(We[k * HC + h * CC + c], atte[h * CC + c], s);
            d_Ve[k * HH + h] = s;
        }
        return;
    }
    __shared__ int s64;
    if (threadIdx.x == 0) {
        int z = 1;
        #pragma unroll
        for (int i = 1; i < 64; i += 2) z &= (ei32[i] == 0);
        s64 = z;
    }
    __syncthreads();
    int e = blockIdx.x * 256 + threadIdx.x;
    if (e < EE) {
        int src, dst;
        if (s64) {
            src = ei32[2 * (size_t)e];
            dst = ei32[2 * ((size_t)EE + e)];
        } else {
            src = ei32[e];
            dst = ei32[EE + e];
        }
        d_esrc[e] = src;
        d_edst[e] = dst;
        atomicAdd(&d_deg[dst], 1);
    }
}

// single-block exclusive scan over (deg + 1 self-loop) -> rowptr & cursor
__global__ void scan_kernel() {
    __shared__ int warpsum[32];
    __shared__ int s_carry;
    int t = threadIdx.x;
    if (t == 0) s_carry = 0;
    __syncthreads();
    for (int base = 0; base < NN; base += 1024) {
        int i = base + t;
        int v = (i < NN) ? (d_deg[i] + 1) : 0;   // +1: self loop
        int lane = t & 31, w = t >> 5;
        int x = v;
        #pragma unroll
        for (int o = 1; o < 32; o <<= 1) {
            int y = __shfl_up_sync(0xffffffffu, x, o);
            if (lane >= o) x += y;
        }
        if (lane == 31) warpsum[w] = x;
        __syncthreads();
        if (w == 0) {
            int s = warpsum[lane];
            #pragma unroll
            for (int o = 1; o < 32; o <<= 1) {
                int y = __shfl_up_sync(0xffffffffu, s, o);
                if (lane >= o) s += y;
            }
            warpsum[lane] = s;
        }
        __syncthreads();
        int incl = x + (w > 0 ? warpsum[w - 1] : 0);
        int excl = incl - v;
        int carry = s_carry;
        if (i < NN) { d_rowptr[i] = carry + excl; d_cursor[i] = carry + excl; }
        __syncthreads();
        if (t == 1023) s_carry = carry + incl;
        __syncthreads();
    }
    if (t == 0) d_rowptr[NN] = s_carry;
}

__global__ void scatter_kernel() {
    int idx = blockIdx.x * blockDim.x + threadIdx.x;
    if (idx >= ET) return;
    int src, dst;
    if (idx < EE) { src = d_esrc[idx]; dst = d_edst[idx]; }
    else          { src = dst = idx - EE; }
    int p = atomicAdd(&d_cursor[dst], 1);
    d_csr_src[p] = src;
    d_csr_eid[p] = idx;
}

// PyG add_self_loops fill_value='mean': per-dst mean of incoming edge_attr
__global__ void loop_mean_kernel(const float* __restrict__ ea) {
    int n = blockIdx.x * 8 + (threadIdx.x >> 5);
    if (n >= NN) return;
    int lane = threadIdx.x & 31;
    int beg = d_rowptr[n], end = d_rowptr[n + 1];
    float s = 0.f;
    for (int p = beg; p < end; p++) {
        int eid = d_csr_eid[p];
        if (eid < EE) s += ea[(size_t)eid * CC + lane];
    }
    float cnt = (float)(end - beg - 1);   // self-loop excluded
    d_loop_attr[n * CC + lane] = s / fmaxf(cnt, 1.f);
}

// a_e[e,h] = edge_attr_full[e,:] @ V_e[:,h]   (rows staged once in smem)
__global__ void __launch_bounds__(384) ae_kernel(const float* __restrict__ ea) {
    __shared__ float s_row[32 * 33];
    __shared__ float sVe[CC * HH];
    int t = threadIdx.x;
    for (int i = t; i < CC * HH; i += 384) sVe[i] = d_Ve[i];
    int e0 = blockIdx.x * 32;
    int nrows = min(32, ET - e0);
    const float* gsrc = (e0 < EE) ? (ea + (size_t)e0 * CC)
                                  : (d_loop_attr + (size_t)(e0 - EE) * CC);
    for (int i = t; i < nrows * CC; i += 384) {
        int r = i >> 5, c = i & 31;
        s_row[r * 33 + c] = gsrc[i];
    }
    __syncthreads();
    if (t < nrows * HH) {
        int el = t / HH, hh = t - HH * el;
        float s = 0.f;
        #pragma unroll
        for (int k = 0; k < CC; k++)
            s = fmaf(s_row[el * 33 + k], sVe[k * HH + hh], s);
        d_ae[(size_t)(e0 + el) * HH + hh] = s;
    }
}

// ---------------- fp32 -> bf16 big/small split conversions --------------------
__global__ void convx_kernel(const float* __restrict__ x) {
    int idx = blockIdx.x * blockDim.x + threadIdx.x;
    if (idx >= NN * FIN) return;
    float v = x[idx];
    __nv_bfloat16 b = __float2bfloat16(v);
    d_xb[idx] = b;
    d_xs[idx] = __float2bfloat16(v - __bfloat162float(b));
}
#define W1ELTS (FIN * HC)
#define W2ELTS (HC * HC)
__global__ void wt_kernel(const float* __restrict__ W1,
                          const float* __restrict__ W2) {
    int idx = blockIdx.x * blockDim.x + threadIdx.x;
    if (idx < W1ELTS) {
        int k = idx / HC, n = idx - HC * (idx / HC);
        float v = W1[idx];
        __nv_bfloat16 b = __float2bfloat16(v);
        d_w1b[(size_t)n * FIN + k] = b;
        d_w1s[(size_t)n * FIN + k] = __float2bfloat16(v - __bfloat162float(b));
    } else if (idx < W1ELTS + W2ELTS) {
        int i2 = idx - W1ELTS;
        int k = i2 / HC, n = i2 - HC * (i2 / HC);
        float v = W2[i2];
        __nv_bfloat16 b = __float2bfloat16(v);
        d_w2b[(size_t)n * HC + k] = b;
        d_w2s[(size_t)n * HC + k] = __float2bfloat16(v - __bfloat162float(b));
    }
}

// ---------------- bf16 mma.sync GEMM (3x split) + fused dots, cp.async -------
#define BM 128
#define BN 128
#define BKK 64
#define ASTR 72
#define TILE_B (128 * ASTR * 2)
#define GEMM_SMEM (8 * TILE_B)   // 147456 bytes

__device__ __forceinline__ void cp16(uint32_t saddr, const void* g) {
    asm volatile("cp.async.ca.shared.global [%0], [%1], 16;"
                 :: "r"(saddr), "l"(g));
}
__device__ __forceinline__ void mma16816(float* c, const uint32_t* a,
                                         const uint32_t* b) {
    asm volatile(
        "mma.sync.aligned.m16n8k16.row.col.f32.bf16.bf16.f32 "
        "{%0,%1,%2,%3}, {%4,%5,%6,%7}, {%8,%9}, {%0,%1,%2,%3};\n"
        : "+f"(c[0]), "+f"(c[1]), "+f"(c[2]), "+f"(c[3])
        : "r"(a[0]), "r"(a[1]), "r"(a[2]), "r"(a[3]), "r"(b[0]), "r"(b[1]));
}

__global__ void __launch_bounds__(256) gemm_kernel(
    int which, const float* __restrict__ attS, const float* __restrict__ attD) {
    extern __shared__ char smem[];
    uint32_t sbase = (uint32_t)__cvta_generic_to_shared(smem);

    const int Kt = which ? HC : FIN;
    const __nv_bfloat16* Ab  = which ? d_h1b : d_xb;
    const __nv_bfloat16* As_ = which ? d_h1s : d_xs;
    const __nv_bfloat16* Bb  = which ? d_w2b : d_w1b;
    const __nv_bfloat16* Bs  = which ? d_w2s : d_w1s;
    float* Cm   = which ? d_hx2 : d_hx1;
    float* as_o = which ? d_as2 : d_as1;
    float* ad_o = which ? d_ad2 : d_ad1;

    int tid = threadIdx.x;
    int wid = tid >> 5, lane = tid & 31;
    int wm = (wid & 3) * 32;
    int wn = (wid >> 2) * 64;
    int tq = lane >> 2, tr = lane & 3;

    int bm = blockIdx.y * BM;
    int bn = blockIdx.x * BN;

    int lrow = tid >> 1;
    int lcol = (tid & 1) * 32;
    const char* gAb = (const char*)(Ab  + (size_t)(bm + lrow) * Kt + lcol);
    const char* gAs = (const char*)(As_ + (size_t)(bm + lrow) * Kt + lcol);
    const char* gBb = (const char*)(Bb  + (size_t)(bn + lrow) * Kt + lcol);
    const char* gBs = (const char*)(Bs  + (size_t)(bn + lrow) * Kt + lcol);
    uint32_t srow = (uint32_t)(lrow * (ASTR * 2) + lcol * 2);

    auto issue = [&](int kt, int st) {
        int kb = kt * BKK * 2;
        uint32_t s0 = sbase + (uint32_t)st * (4 * TILE_B) + srow;
        #pragma unroll
        for (int i = 0; i < 4; i++) {
            cp16(s0 + 0 * TILE_B + i * 16, gAb + kb + i * 16);
            cp16(s0 + 1 * TILE_B + i * 16, gAs + kb + i * 16);
            cp16(s0 + 2 * TILE_B + i * 16, gBb + kb + i * 16);
            cp16(s0 + 3 * TILE_B + i * 16, gBs + kb + i * 16);
        }
        asm volatile("cp.async.commit_group;");
    };

    float acc[2][8][4];
    #pragma unroll
    for (int mt = 0; mt < 2; mt++)
        #pragma unroll
        for (int nt = 0; nt < 8; nt++)
            #pragma unroll
            for (int q = 0; q < 4; q++) acc[mt][nt][q] = 0.f;

    const int KT = Kt / BKK;
    issue(0, 0);

    for (int kt = 0; kt < KT; kt++) {
        int st = kt & 1;
        if (kt + 1 < KT) {
            issue(kt + 1, st ^ 1);
            asm volatile("cp.async.wait_group 1;");
        } else {
            asm volatile("cp.async.wait_group 0;");
        }
        __syncthreads();

        const __nv_bfloat16* cAb = (const __nv_bfloat16*)(smem + st * 4 * TILE_B);
        const __nv_bfloat16* cAs = (const __nv_bfloat16*)(smem + st * 4 * TILE_B + TILE_B);
        const __nv_bfloat16* cBb = (const __nv_bfloat16*)(smem + st * 4 * TILE_B + 2 * TILE_B);
        const __nv_bfloat16* cBs = (const __nv_bfloat16*)(smem + st * 4 * TILE_B + 3 * TILE_B);

        #pragma unroll
        for (int s = 0; s < BKK / 16; s++) {
            int kk = s * 16 + tr * 2;
            uint32_t afb[2][4], afs[2][4];
            #pragma unroll
            for (int mt = 0; mt < 2; mt++) {
                int r0 = wm + mt * 16 + tq;
                afb[mt][0] = *(const uint32_t*)&cAb[r0 * ASTR + kk];
                afb[mt][1] = *(const uint32_t*)&cAb[(r0 + 8) * ASTR + kk];
                afb[mt][2] = *(const uint32_t*)&cAb[r0 * ASTR + kk + 8];
                afb[mt][3] = *(const uint32_t*)&cAb[(r0 + 8) * ASTR + kk + 8];
                afs[mt][0] = *(const uint32_t*)&cAs[r0 * ASTR + kk];
                afs[mt][1] = *(const uint32_t*)&cAs[(r0 + 8) * ASTR + kk];
                afs[mt][2] = *(const uint32_t*)&cAs[r0 * ASTR + kk + 8];
                afs[mt][3] = *(const uint32_t*)&cAs[(r0 + 8) * ASTR + kk + 8];
            }
            #pragma unroll
            for (int nt = 0; nt < 8; nt++) {
                int nr = wn + nt * 8 + tq;
                uint32_t bfb[2], bfs[2];
                bfb[0] = *(const uint32_t*)&cBb[nr * ASTR + kk];
                bfb[1] = *(const uint32_t*)&cBb[nr * ASTR + kk + 8];
                bfs[0] = *(const uint32_t*)&cBs[nr * ASTR + kk];
                bfs[1] = *(const uint32_t*)&cBs[nr * ASTR + kk + 8];
                #pragma unroll
                for (int mt = 0; mt < 2; mt++) {
                    mma16816(acc[mt][nt], afb[mt], bfb);
                    mma16816(acc[mt][nt], afb[mt], bfs);
                    mma16816(acc[mt][nt], afs[mt], bfb);
                }
            }
        }
        __syncthreads();
    }

    // ---- epilogue: store C + fused per-head attention dots ----
    float sD[2][2][2], dD[2][2][2];
    #pragma unroll
    for (int mt = 0; mt < 2; mt++)
        #pragma unroll
        for (int hf = 0; hf < 2; hf++)
            #pragma unroll
            for (int hd = 0; hd < 2; hd++) { sD[mt][hf][hd] = 0.f; dD[mt][hf][hd] = 0.f; }

    #pragma unroll
    for (int mt = 0; mt < 2; mt++) {
        int r0 = bm + wm + mt * 16 + tq;
        #pragma unroll
        for (int nt = 0; nt < 8; nt++) {
            int c0 = bn + wn + nt * 8 + tr * 2;
            int hd = nt >> 2;
            float aS0 = attS[c0], aS1 = attS[c0 + 1];
            float aD0 = attD[c0], aD1 = attD[c0 + 1];
            sD[mt][0][hd] += acc[mt][nt][0] * aS0 + acc[mt][nt][1] * aS1;
            sD[mt][1][hd] += acc[mt][nt][2] * aS0 + acc[mt][nt][3] * aS1;
            dD[mt][0][hd] += acc[mt][nt][0] * aD0 + acc[mt][nt][1] * aD1;
            dD[mt][1][hd] += acc[mt][nt][2] * aD0 + acc[mt][nt][3] * aD1;
            if (r0 < NN)
                *(float2*)&Cm[(size_t)r0 * HC + c0] =
                    make_float2(acc[mt][nt][0], acc[mt][nt][1]);
            if (r0 + 8 < NN)
                *(float2*)&Cm[(size_t)(r0 + 8) * HC + c0] =
                    make_float2(acc[mt][nt][2], acc[mt][nt][3]);
        }
    }
    #pragma unroll
    for (int mt = 0; mt < 2; mt++)
        #pragma unroll
        for (int hf = 0; hf < 2; hf++)
            #pragma unroll
            for (int hd = 0; hd < 2; hd++) {
                float s = sD[mt][hf][hd], d = dD[mt][hf][hd];
                s += __shfl_xor_sync(0xffffffffu, s, 1);
                s += __shfl_xor_sync(0xffffffffu, s, 2);
                d += __shfl_xor_sync(0xffffffffu, d, 1);
                d += __shfl_xor_sync(0xffffffffu, d, 2);
                sD[mt][hf][hd] = s; dD[mt][hf][hd] = d;
            }
    if (tr == 0) {
        int hbase = (bn + wn) >> 5;
        #pragma unroll
        for (int mt = 0; mt < 2; mt++)
            #pragma unroll
            for (int hf = 0; hf < 2; hf++) {
                int row = bm + wm + mt * 16 + tq + hf * 8;
                if (row < NN) {
                    #pragma unroll
                    for (int hd = 0; hd < 2; hd++) {
                        as_o[row * HH + hbase + hd] = sD[mt][hf][hd];
                        ad_o[row * HH + hbase + hd] = dD[mt][hf][hd];
                    }
                }
            }
    }
}

// ---------------- layer-1 aggregation: single pass, deferred normalization ---
__global__ void __launch_bounds__(HC) agg1_kernel(const float* __restrict__ b1) {
    int n = blockIdx.x;
    int t = threadIdx.x;
    int h = t >> 5;
    __shared__ float s_ad[HH], s_den[HH];
    __shared__ int   s_src[CHUNK];
    __shared__ float s_alpha[CHUNK * HH];

    int beg = d_rowptr[n], deg = d_rowptr[n + 1] - beg;
    if (t < HH) { s_ad[t] = d_ad1[n * HH + t]; s_den[t] = 0.f; }
    __syncthreads();

    float acc = 0.f;
    float den_loc = 0.f;
    for (int base = 0; base < deg; base += CHUNK) {
        int cn = min(CHUNK, deg - base);
        for (int idx = t; idx < cn * HH; idx += HC) {
            int j = idx / HH, hh = idx - HH * j;
            int p = beg + base + j;
            int src = d_csr_src[p], eid = d_csr_eid[p];
            float e = d_as1[src * HH + hh] + s_ad[hh] + d_ae[(size_t)eid * HH + hh];
            e = (e > 0.f) ? e : NEG_SLOPE * e;
            float ex = __expf(e);
            s_alpha[j * HH + hh] = ex;
            den_loc += ex;
            if (hh == 0) s_src[j] = src;
        }
        __syncthreads();
        #pragma unroll 8
        for (int j = 0; j < cn; j++)
            acc = fmaf(s_alpha[j * HH + h], d_hx1[(size_t)s_src[j] * HC + t], acc);
        __syncthreads();
    }
    atomicAdd(&s_den[t % HH], den_loc);
    __syncthreads();

    float v = acc / s_den[h] + b1[t];
    v = (v > 0.f) ? v : expm1f(v);                 // ELU
    __nv_bfloat16 big = __float2bfloat16(v);
    d_h1b[(size_t)n * HC + t] = big;
    d_h1s[(size_t)n * HC + t] = __float2bfloat16(v - __bfloat162float(big));
}

// ---------------- layer-2 aggregation (mean over heads + log_softmax) --------
__global__ void __launch_bounds__(HC) agg2_kernel(const float* __restrict__ b2,
                                                  float* __restrict__ out,
                                                  int out_size) {
    int n = blockIdx.x;
    int t = threadIdx.x;
    int h = t >> 5;
    __shared__ float s_ad[HH], s_den[HH];
    __shared__ int   s_src[CHUNK];
    __shared__ float s_alpha[CHUNK * HH];
    __shared__ float s_out[HC];

    int beg = d_rowptr[n], deg = d_rowptr[n + 1] - beg;
    if (t < HH) { s_ad[t] = d_ad2[n * HH + t]; s_den[t] = 0.f; }
    __syncthreads();

    float acc = 0.f;
    float den_loc = 0.f;
    for (int base = 0; base < deg; base += CHUNK) {
        int cn = min(CHUNK, deg - base);
        for (int idx = t; idx < cn * HH; idx += HC) {
            int j = idx / HH, hh = idx - HH * j;
            int src = d_csr_src[beg + base + j];
            float e = d_as2[src * HH + hh] + s_ad[hh];
            e = (e > 0.f) ? e : NEG_SLOPE * e;
            float ex = __expf(e);
            s_alpha[j * HH + hh] = ex;
            den_loc += ex;
            if (hh == 0) s_src[j] = src;
        }
        __syncthreads();
        #pragma unroll 8
        for (int j = 0; j < cn; j++)
            acc = fmaf(s_alpha[j * HH + h], d_hx2[(size_t)s_src[j] * HC + t], acc);
        __syncthreads();
    }
    atomicAdd(&s_den[t % HH], den_loc);
    __syncthreads();

    s_out[t] = acc / s_den[h];
    __syncthreads();
    if (t < CC) {
        float s = 0.f;
        #pragma unroll
        for (int hh = 0; hh < HH; hh++) s += s_out[hh * CC + t];
        float val = s * (1.f / (float)HH) + b2[t];
        float m = val;
        #pragma unroll
        for (int o = 16; o > 0; o >>= 1)
            m = fmaxf(m, __shfl_xor_sync(0xffffffffu, m, o));
        float ex = __expf(val - m);
        float ssum = ex;
        #pragma unroll
        for (int o = 16; o > 0; o >>= 1)
            ssum += __shfl_xor_sync(0xffffffffu, ssum, o);
        float lse = m + logf(ssum);
        int i0 = n * CC + t;
        if (i0 < out_size) out[i0] = val;                 // h2
        int i1 = NN * CC + i0;
        if (i1 < out_size) out[i1] = val - lse;           // log_softmax(h2)
    }
}

// ---------------- launch: two-stream fork/join --------------------------------
extern "C" void kernel_launch(void* const* d_in, const int* in_sizes, int n_in,
                              void* d_out, int out_size) {
    const float* x     = (const float*)d_in[0];
    const int*   ei32  = (const int*)d_in[1];
    const float* ea    = (const float*)d_in[2];
    const float* W1    = (const float*)d_in[3];
    const float* attS1 = (const float*)d_in[4];
    const float* attD1 = (const float*)d_in[5];
    const float* We1   = (const float*)d_in[6];
    const float* attE1 = (const float*)d_in[7];
    const float* b1    = (const float*)d_in[8];
    const float* W2    = (const float*)d_in[9];
    const float* attS2 = (const float*)d_in[10];
    const float* attD2 = (const float*)d_in[11];
    const float* b2    = (const float*)d_in[12];
    float* out = (float*)d_out;

    // One-time resources (created on the uncaptured correctness call).
    static cudaStream_t sB = nullptr;
    static cudaEvent_t  evF = nullptr, evJ = nullptr;
    if (sB == nullptr) {
        cudaFuncSetAttribute(gemm_kernel,
                             cudaFuncAttributeMaxDynamicSharedMemorySize, GEMM_SMEM);
        cudaStreamCreateWithFlags(&sB, cudaStreamNonBlocking);
        cudaEventCreateWithFlags(&evF, cudaEventDisableTiming);
        cudaEventCreateWithFlags(&evJ, cudaEventDisableTiming);
    }

    // fork: stream B runs the feature/GEMM chain
    cudaEventRecord(evF, 0);
    cudaStreamWaitEvent(sB, evF, 0);

    convx_kernel<<<(NN * FIN + 255) / 256, 256, 0, sB>>>(x);
    wt_kernel<<<(W1ELTS + W2ELTS + 255) / 256, 256, 0, sB>>>(W1, W2);
    gemm_kernel<<<dim3(HC / BN, NPAD / BM), 256, GEMM_SMEM, sB>>>(0, attS1, attD1);
    cudaEventRecord(evJ, sB);

    // default stream: edge/CSR chain (independent of the GEMM chain)
    zero_deg_kernel<<<(NN + 255) / 256, 256>>>();
    convert_kernel<<<(EE + 255) / 256 + 1, 256>>>(ei32, We1, attE1);
    scan_kernel<<<1, 1024>>>();
    scatter_kernel<<<(ET + 255) / 256, 256>>>();
    loop_mean_kernel<<<(NN + 7) / 8, 256>>>(ea);
    ae_kernel<<<(ET + 31) / 32, 384>>>(ea);

    // join, then the serial tail
    cudaStreamWaitEvent(0, evJ, 0);
    agg1_kernel<<<NN, HC>>>(b1);
    gemm_kernel<<<dim3(HC / BN, NPAD / BM), 256, GEMM_SMEM>>>(1, attS2, attD2);
    agg2_kernel<<<NN, HC>>>(b2, out, out_size);
}